// round 10
// baseline (speedup 1.0000x reference)
#include <cuda_runtime.h>
#include <cuda_bf16.h>
#include <cuda_fp16.h>
#include <cstdint>
#include <math.h>

// ---------------- problem constants ----------------
#define E_NUM      8
#define TOPK       2
#define IN_D       1024
#define HD         2048
#define NTOK       16384
#define NK         32768
#define CAP        5120
#define ROUTE_BLOCKS 2048

// ---------------- device scratch ----------------
__device__ __half g_xh[(size_t)NTOK * IN_D];
__device__ __half g_w1h[(size_t)E_NUM * HD * IN_D];
__device__ __half g_wgh[(size_t)E_NUM * HD * IN_D];
__device__ __half g_w2h[(size_t)E_NUM * IN_D * HD];
__device__ __half g_hh[(size_t)E_NUM * CAP * HD];
__device__ __half g_buf_out[(size_t)E_NUM * CAP * IN_D];
__device__ int   g_exp[NK];
__device__ float g_w[NK];
__device__ int   g_slot[NK];
__device__ int   g_slot_token[E_NUM * CAP];
__device__ int   g_counts[E_NUM];
__device__ int   g_kept[E_NUM];
__device__ float g_prob_part[ROUTE_BLOCKS * E_NUM];

// ---------------- PTX helpers ----------------
__device__ __forceinline__ uint32_t smem_u32(const void* p) {
    uint32_t a;
    asm("{ .reg .u64 t; cvta.to.shared.u64 t, %1; cvt.u32.u64 %0, t; }" : "=r"(a) : "l"(p));
    return a;
}

#define CPA16(dst, src) \
    asm volatile("cp.async.cg.shared.global [%0], [%1], 16;" :: "r"(dst), "l"(src) : "memory")

#define LDSM4(r, addr) \
    asm volatile("ldmatrix.sync.aligned.m8n8.x4.shared.b16 {%0,%1,%2,%3}, [%4];" \
        : "=r"((r)[0]), "=r"((r)[1]), "=r"((r)[2]), "=r"((r)[3]) : "r"(addr))

#define MMA_F16(d, a, bb) \
    asm volatile("mma.sync.aligned.m16n8k16.row.col.f32.f16.f16.f32 " \
        "{%0,%1,%2,%3}, {%4,%5,%6,%7}, {%8,%9}, {%0,%1,%2,%3};" \
        : "+f"((d)[0]), "+f"((d)[1]), "+f"((d)[2]), "+f"((d)[3]) \
        : "r"((a)[0]), "r"((a)[1]), "r"((a)[2]), "r"((a)[3]), \
          "r"((bb)[0]), "r"((bb)[1]))

// ============================================================
// 0) fp32 -> fp16 convert: all four tensors in one launch
//    grid = 4 segments x 2048 blocks
// ============================================================
__global__ __launch_bounds__(256) void conv_all_kernel(const float4* __restrict__ x,
                                                       const float4* __restrict__ w1,
                                                       const float4* __restrict__ wg,
                                                       const float4* __restrict__ w2,
                                                       int n4)
{
    int seg = blockIdx.x >> 11;          // 0..3
    int b   = blockIdx.x & 2047;
    const float4* in;
    __half* dst;
    switch (seg) {
        case 0: in = x;  dst = g_xh;  break;
        case 1: in = w1; dst = g_w1h; break;
        case 2: in = wg; dst = g_wgh; break;
        default: in = w2; dst = g_w2h; break;
    }
    uint2* d4 = (uint2*)dst;
    for (int i = b * blockDim.x + threadIdx.x; i < n4; i += 2048 * blockDim.x) {
        float4 v = in[i];
        __half2 h01 = __halves2half2(__float2half_rn(v.x), __float2half_rn(v.y));
        __half2 h23 = __halves2half2(__float2half_rn(v.z), __float2half_rn(v.w));
        uint2 o;
        o.x = *reinterpret_cast<uint32_t*>(&h01);
        o.y = *reinterpret_cast<uint32_t*>(&h23);
        d4[i] = o;
    }
}

// ============================================================
// 1) routing
// ============================================================
__global__ __launch_bounds__(256) void route_kernel(const float* __restrict__ x,
                                                    const float* __restrict__ gate_w)
{
    __shared__ float sg[E_NUM * IN_D];
    __shared__ float pp[8][E_NUM];
    for (int i = threadIdx.x; i < E_NUM * IN_D; i += blockDim.x) sg[i] = gate_w[i];
    __syncthreads();

    int w = threadIdx.x >> 5, lane = threadIdx.x & 31;
    int t = blockIdx.x * 8 + w;
    const float* xr = x + (size_t)t * IN_D;
    float acc[E_NUM];
#pragma unroll
    for (int e = 0; e < E_NUM; e++) acc[e] = 0.f;
    for (int j = 0; j < IN_D / 32; j++) {
        float xv = xr[lane + j * 32];
#pragma unroll
        for (int e = 0; e < E_NUM; e++) acc[e] += xv * sg[e * IN_D + lane + j * 32];
    }
#pragma unroll
    for (int off = 16; off > 0; off >>= 1)
#pragma unroll
        for (int e = 0; e < E_NUM; e++) acc[e] += __shfl_down_sync(0xffffffffu, acc[e], off);

    if (lane == 0) {
        float m = acc[0];
#pragma unroll
        for (int e = 1; e < E_NUM; e++) m = fmaxf(m, acc[e]);
        float p[E_NUM], s = 0.f;
#pragma unroll
        for (int e = 0; e < E_NUM; e++) { p[e] = expf(acc[e] - m); s += p[e]; }
        float inv = 1.f / s;
#pragma unroll
        for (int e = 0; e < E_NUM; e++) p[e] *= inv;
        int e1 = 0;
#pragma unroll
        for (int e = 1; e < E_NUM; e++) if (p[e] > p[e1]) e1 = e;
        int e2 = (e1 == 0) ? 1 : 0;
#pragma unroll
        for (int e = 0; e < E_NUM; e++) if (e != e1 && p[e] > p[e2]) e2 = e;
        float denom = p[e1] + p[e2] + 1e-9f;
        g_exp[2 * t] = e1; g_exp[2 * t + 1] = e2;
        g_w[2 * t] = p[e1] / denom; g_w[2 * t + 1] = p[e2] / denom;
#pragma unroll
        for (int e = 0; e < E_NUM; e++) pp[w][e] = p[e];
    }
    __syncthreads();
    if (threadIdx.x < E_NUM) {
        float s = 0.f;
        for (int ww = 0; ww < 8; ww++) s += pp[ww][threadIdx.x];
        g_prob_part[blockIdx.x * E_NUM + threadIdx.x] = s;
    }
}

// ============================================================
// 2) dispatch
// ============================================================
__global__ __launch_bounds__(1024) void dispatch_kernel()
{
    __shared__ int sc[1024 * E_NUM];
    int tid = threadIdx.x, base = tid * 32;
    int h[E_NUM];
#pragma unroll
    for (int e = 0; e < E_NUM; e++) h[e] = 0;
    for (int i = 0; i < 32; i++) h[g_exp[base + i]]++;
#pragma unroll
    for (int e = 0; e < E_NUM; e++) sc[tid * E_NUM + e] = h[e];
    __syncthreads();
    for (int off = 1; off < 1024; off <<= 1) {
        int v[E_NUM];
        if (tid >= off)
#pragma unroll
            for (int e = 0; e < E_NUM; e++) v[e] = sc[(tid - off) * E_NUM + e];
        __syncthreads();
        if (tid >= off)
#pragma unroll
            for (int e = 0; e < E_NUM; e++) sc[tid * E_NUM + e] += v[e];
        __syncthreads();
    }
    int basec[E_NUM];
#pragma unroll
    for (int e = 0; e < E_NUM; e++) basec[e] = sc[tid * E_NUM + e] - h[e];
    if (tid == 1023)
#pragma unroll
        for (int e = 0; e < E_NUM; e++) {
            int c = sc[tid * E_NUM + e];
            g_counts[e] = c;
            g_kept[e] = (c < CAP) ? c : CAP;
        }
    for (int i = 0; i < 32; i++) {
        int idx = base + i;
        int e = g_exp[idx];
        int pos = basec[e]++;
        if (pos < CAP) {
            int s = e * CAP + pos;
            g_slot[idx] = s;
            g_slot_token[s] = idx >> 1;
        } else g_slot[idx] = -1;
    }
}

// ============================================================
// 3) loss
// ============================================================
__global__ void loss_kernel(float* out_loss)
{
    __shared__ float ps[E_NUM];
    if (threadIdx.x < E_NUM) {
        float s = 0.f;
        for (int b = 0; b < ROUTE_BLOCKS; b++) s += g_prob_part[b * E_NUM + threadIdx.x];
        float p = s / (float)NTOK;
        float f = (float)g_counts[threadIdx.x] / (float)NK;
        ps[threadIdx.x] = p * f;
    }
    __syncthreads();
    if (threadIdx.x == 0 && out_loss) {
        float s = 0.f;
#pragma unroll
        for (int e = 0; e < E_NUM; e++) s += ps[e];
        *out_loss = (float)E_NUM * s;
    }
}

// ============================================================
// GEMM tiling: 128x128 tile, BK=32, 8 warps (64x32 warp tile)
// smem rows padded to 80B; single-barrier depth-3 pipeline, 4 slots
// Persistent CTAs: flattened tile loop, n-fastest
// ============================================================
#define LDSROW 80
#define CSZ    (128 * LDSROW)   // 10240 B per component tile

// ============================================================
// 4) GEMM1 (persistent): h = silu(Xg.fc1^T) * (Xg.gating^T), K=1024
//    tiles: 8 experts x 40 m x 16 n = 5120
// ============================================================
__global__ __launch_bounds__(256, 1) void gemm1_mma()
{
    extern __shared__ char smem[];
    uint32_t sb = smem_u32(smem);
    int tid = threadIdx.x, lane = tid & 31, wid = tid >> 5;
    int wm = wid & 1, wn = wid >> 1;

    uint32_t a_off[4], b_off[2];
#pragma unroll
    for (int mi = 0; mi < 4; mi++)
        a_off[mi] = (wm * 64 + mi * 16 + (lane & 15)) * LDSROW + (lane >> 4) * 16;
#pragma unroll
    for (int ni = 0; ni < 2; ni++)
        b_off[ni] = (wn * 32 + ni * 16 + (lane & 7) + ((lane >> 4) << 3)) * LDSROW
                    + ((lane >> 3) & 1) * 16;

    const int STG = 3 * CSZ;   // 30720 per slot, 4 slots

    for (int t = blockIdx.x; t < 5120; t += gridDim.x) {
        int e = t / 640;
        int rem = t - e * 640;
        int m0 = (rem >> 4) * 128;
        int n0 = (rem & 15) * 128;
        int kept = g_kept[e];
        if (m0 >= kept) continue;

        const __half* gsrc[6];
        uint32_t sdst[6];
#pragma unroll
        for (int ci = 0; ci < 2; ci++) {
            int c = tid + ci * 256;
            int row = c >> 2, kc = c & 3;
            int tok = g_slot_token[e * CAP + m0 + row] & (NTOK - 1);
            size_t ar = (size_t)tok * IN_D + kc * 8;
            size_t br = ((size_t)e * HD + n0 + row) * IN_D + kc * 8;
            gsrc[ci * 3 + 0] = g_xh + ar;
            gsrc[ci * 3 + 1] = g_w1h + br;
            gsrc[ci * 3 + 2] = g_wgh + br;
            uint32_t sd = sb + row * LDSROW + kc * 16;
#pragma unroll
            for (int comp = 0; comp < 3; comp++) sdst[ci * 3 + comp] = sd + comp * CSZ;
        }

        auto load_stage = [&](int slab, int st) {
            int ko = slab * 32;
            uint32_t so = st * STG;
#pragma unroll
            for (int i = 0; i < 6; i++) CPA16(sdst[i] + so, gsrc[i] + ko);
            asm volatile("cp.async.commit_group;" ::: "memory");
        };
        load_stage(0, 0);
        load_stage(1, 1);
        load_stage(2, 2);

        float acc1[4][4][4], acc2[4][4][4];
#pragma unroll
        for (int mi = 0; mi < 4; mi++)
#pragma unroll
            for (int nj = 0; nj < 4; nj++)
#pragma unroll
                for (int q = 0; q < 4; q++) { acc1[mi][nj][q] = 0.f; acc2[mi][nj][q] = 0.f; }

        for (int s = 0; s < 32; s++) {
            int st = s & 3;
            if (s < 29) asm volatile("cp.async.wait_group 2;" ::: "memory");
            else        asm volatile("cp.async.wait_group 0;" ::: "memory");
            __syncthreads();
            if (s < 29) load_stage(s + 3, (s + 3) & 3);
            uint32_t base = sb + st * STG;
#pragma unroll
            for (int ks = 0; ks < 2; ks++) {
                uint32_t kb = ks * 32;
                uint32_t Ah[4][4], B1[2][4], B2[2][4];
#pragma unroll
                for (int mi = 0; mi < 4; mi++) LDSM4(Ah[mi], base + a_off[mi] + kb);
#pragma unroll
                for (int ni = 0; ni < 2; ni++) LDSM4(B1[ni], base + CSZ + b_off[ni] + kb);
#pragma unroll
                for (int ni = 0; ni < 2; ni++) LDSM4(B2[ni], base + 2 * CSZ + b_off[ni] + kb);
#pragma unroll
                for (int mi = 0; mi < 4; mi++)
#pragma unroll
                    for (int ni = 0; ni < 2; ni++)
#pragma unroll
                        for (int hh = 0; hh < 2; hh++) {
                            int nj = ni * 2 + hh;
                            MMA_F16(acc1[mi][nj], Ah[mi], B1[ni] + hh * 2);
                            MMA_F16(acc2[mi][nj], Ah[mi], B2[ni] + hh * 2);
                        }
            }
        }

        // SwiGLU epilogue -> fp16 h
#pragma unroll
        for (int mi = 0; mi < 4; mi++) {
            int rbase = m0 + wm * 64 + mi * 16 + (lane >> 2);
#pragma unroll
            for (int rr = 0; rr < 2; rr++) {
                int r = rbase + rr * 8;
                if (r < kept) {
                    size_t ro = (size_t)(e * CAP + r) * HD;
#pragma unroll
                    for (int nj = 0; nj < 4; nj++) {
                        int col = n0 + wn * 32 + nj * 8 + (lane & 3) * 2;
                        float v0 = acc1[mi][nj][rr * 2 + 0], v1 = acc1[mi][nj][rr * 2 + 1];
                        float g0 = acc2[mi][nj][rr * 2 + 0], g1 = acc2[mi][nj][rr * 2 + 1];
                        float h0 = v0 / (1.f + __expf(-v0)) * g0;
                        float h1 = v1 / (1.f + __expf(-v1)) * g1;
                        *(__half2*)(g_hh + ro + col) =
                            __halves2half2(__float2half_rn(h0), __float2half_rn(h1));
                    }
                }
            }
        }
        __syncthreads();
    }
}

// ============================================================
// 5) GEMM2 (persistent): out = H . fc2^T, K=2048
//    tiles: 8 experts x 40 m x 8 n = 2560; 2 CTAs/SM
// ============================================================
__global__ __launch_bounds__(256, 2) void gemm2_mma()
{
    extern __shared__ char smem[];
    uint32_t sb = smem_u32(smem);
    int tid = threadIdx.x, lane = tid & 31, wid = tid >> 5;
    int wm = wid & 1, wn = wid >> 1;

    uint32_t a_off[4], b_off[2];
#pragma unroll
    for (int mi = 0; mi < 4; mi++)
        a_off[mi] = (wm * 64 + mi * 16 + (lane & 15)) * LDSROW + (lane >> 4) * 16;
#pragma unroll
    for (int ni = 0; ni < 2; ni++)
        b_off[ni] = (wn * 32 + ni * 16 + (lane & 7) + ((lane >> 4) << 3)) * LDSROW
                    + ((lane >> 3) & 1) * 16;

    const int STG = 2 * CSZ;   // 20480 per slot, 4 slots

    for (int t = blockIdx.x; t < 2560; t += gridDim.x) {
        int e = t / 320;
        int rem = t - e * 320;
        int m0 = (rem >> 3) * 128;
        int n0 = (rem & 7) * 128;
        int kept = g_kept[e];
        if (m0 >= kept) continue;

        const __half* gsrc[4];
        uint32_t sdst[4];
#pragma unroll
        for (int ci = 0; ci < 2; ci++) {
            int c = tid + ci * 256;
            int row = c >> 2, kc = c & 3;
            size_t ar = (size_t)(e * CAP + m0 + row) * HD + kc * 8;
            size_t br = ((size_t)e * IN_D + n0 + row) * HD + kc * 8;
            gsrc[ci * 2 + 0] = g_hh + ar;
            gsrc[ci * 2 + 1] = g_w2h + br;
            uint32_t sd = sb + row * LDSROW + kc * 16;
#pragma unroll
            for (int comp = 0; comp < 2; comp++) sdst[ci * 2 + comp] = sd + comp * CSZ;
        }

        auto load_stage = [&](int slab, int st) {
            int ko = slab * 32;
            uint32_t so = st * STG;
#pragma unroll
            for (int i = 0; i < 4; i++) CPA16(sdst[i] + so, gsrc[i] + ko);
            asm volatile("cp.async.commit_group;" ::: "memory");
        };
        load_stage(0, 0);
        load_stage(1, 1);
        load_stage(2, 2);

        float acc[4][4][4];
#pragma unroll
        for (int mi = 0; mi < 4; mi++)
#pragma unroll
            for (int nj = 0; nj < 4; nj++)
#pragma unroll
                for (int q = 0; q < 4; q++) acc[mi][nj][q] = 0.f;

        for (int s = 0; s < 64; s++) {
            int st = s & 3;
            if (s < 61) asm volatile("cp.async.wait_group 2;" ::: "memory");
            else        asm volatile("cp.async.wait_group 0;" ::: "memory");
            __syncthreads();
            if (s < 61) load_stage(s + 3, (s + 3) & 3);
            uint32_t base = sb + st * STG;
#pragma unroll
            for (int ks = 0; ks < 2; ks++) {
                uint32_t kb = ks * 32;
                uint32_t Ah[4][4], B[2][4];
#pragma unroll
                for (int mi = 0; mi < 4; mi++) LDSM4(Ah[mi], base + a_off[mi] + kb);
#pragma unroll
                for (int ni = 0; ni < 2; ni++) LDSM4(B[ni], base + CSZ + b_off[ni] + kb);
#pragma unroll
                for (int mi = 0; mi < 4; mi++)
#pragma unroll
                    for (int ni = 0; ni < 2; ni++)
#pragma unroll
                        for (int hh = 0; hh < 2; hh++)
                            MMA_F16(acc[mi][ni * 2 + hh], Ah[mi], B[ni] + hh * 2);
            }
        }

#pragma unroll
        for (int mi = 0; mi < 4; mi++) {
            int rbase = m0 + wm * 64 + mi * 16 + (lane >> 2);
#pragma unroll
            for (int rr = 0; rr < 2; rr++) {
                int r = rbase + rr * 8;
                if (r < kept) {
                    size_t ro = (size_t)(e * CAP + r) * IN_D;
#pragma unroll
                    for (int nj = 0; nj < 4; nj++) {
                        int col = n0 + wn * 32 + nj * 8 + (lane & 3) * 2;
                        *(__half2*)(g_buf_out + ro + col) =
                            __halves2half2(__float2half_rn(acc[mi][nj][rr * 2 + 0]),
                                           __float2half_rn(acc[mi][nj][rr * 2 + 1]));
                    }
                }
            }
        }
        __syncthreads();
    }
}

// ============================================================
// 6) combine (fp16 buf): out[t] = w1*buf[s1] + w2*buf[s2]
// ============================================================
__global__ __launch_bounds__(256) void combine_kernel(float* __restrict__ out)
{
    int t = blockIdx.x;
    int s1 = g_slot[2 * t];
    int s2 = g_slot[2 * t + 1];
    float w1 = (s1 >= 0) ? g_w[2 * t] : 0.f;
    float w2 = (s2 >= 0) ? g_w[2 * t + 1] : 0.f;
    const uint2* r1 = (s1 >= 0) ? (const uint2*)(g_buf_out + (size_t)s1 * IN_D) : nullptr;
    const uint2* r2 = (s2 >= 0) ? (const uint2*)(g_buf_out + (size_t)s2 * IN_D) : nullptr;

    int d = threadIdx.x;   // 256 threads x 4 halves = 1024 elems
    float4 v = make_float4(0, 0, 0, 0);
    if (r1) {
        uint2 a = r1[d];
        float2 p = __half22float2(*reinterpret_cast<__half2*>(&a.x));
        float2 q = __half22float2(*reinterpret_cast<__half2*>(&a.y));
        v.x += w1 * p.x; v.y += w1 * p.y; v.z += w1 * q.x; v.w += w1 * q.y;
    }
    if (r2) {
        uint2 a = r2[d];
        float2 p = __half22float2(*reinterpret_cast<__half2*>(&a.x));
        float2 q = __half22float2(*reinterpret_cast<__half2*>(&a.y));
        v.x += w2 * p.x; v.y += w2 * p.y; v.z += w2 * q.x; v.w += w2 * q.y;
    }
    ((float4*)(out + (size_t)t * IN_D))[d] = v;
}

// ============================================================
extern "C" void kernel_launch(void* const* d_in, const int* in_sizes, int n_in,
                              void* d_out, int out_size)
{
    const float* x      = (const float*)d_in[0];
    const float* gate_w = (const float*)d_in[1];
    const float* fc1_w  = (const float*)d_in[2];
    const float* gating = (const float*)d_in[3];
    const float* fc2_w  = (const float*)d_in[4];
    float* out = (float*)d_out;
    float* loss_ptr = (out_size > NTOK * IN_D) ? out + (size_t)NTOK * IN_D : nullptr;

    static int n_sms = 0;
    if (n_sms == 0) {
        int dev = 0;
        cudaGetDevice(&dev);
        cudaDeviceGetAttribute(&n_sms, cudaDevAttrMultiProcessorCount, dev);
        if (n_sms <= 0) n_sms = 148;
        const int smem1 = 4 * 3 * CSZ;   // 122880
        const int smem2 = 4 * 2 * CSZ;   // 81920
        cudaFuncSetAttribute(gemm1_mma, cudaFuncAttributeMaxDynamicSharedMemorySize, smem1);
        cudaFuncSetAttribute(gemm2_mma, cudaFuncAttributeMaxDynamicSharedMemorySize, smem2);
    }
    const int smem1 = 4 * 3 * CSZ;
    const int smem2 = 4 * 2 * CSZ;

    const int n4 = NTOK * IN_D / 4;
    conv_all_kernel<<<8192, 256>>>((const float4*)x, (const float4*)fc1_w,
                                   (const float4*)gating, (const float4*)fc2_w, n4);

    route_kernel<<<ROUTE_BLOCKS, 256>>>(x, gate_w);
    dispatch_kernel<<<1, 1024>>>();
    loss_kernel<<<1, 32>>>(loss_ptr);
    gemm1_mma<<<n_sms, 256, smem1>>>();
    gemm2_mma<<<2 * n_sms, 256, smem2>>>();
    combine_kernel<<<NTOK, 256>>>(out);
}

// round 11
// speedup vs baseline: 1.0964x; 1.0964x over previous
#include <cuda_runtime.h>
#include <cuda_bf16.h>
#include <cuda_fp16.h>
#include <cstdint>
#include <math.h>

// ---------------- problem constants ----------------
#define E_NUM      8
#define TOPK       2
#define IN_D       1024
#define HD         2048
#define NTOK       16384
#define NK         32768
#define CAP        5120
#define ROUTE_BLOCKS 2048

// ---------------- device scratch ----------------
__device__ __half g_xh[(size_t)NTOK * IN_D];
__device__ __half g_w1h[(size_t)E_NUM * HD * IN_D];
__device__ __half g_wgh[(size_t)E_NUM * HD * IN_D];
__device__ __half g_w2h[(size_t)E_NUM * IN_D * HD];
__device__ __half g_hh[(size_t)E_NUM * CAP * HD];
__device__ __half g_buf_out[(size_t)E_NUM * CAP * IN_D];
__device__ int   g_exp[NK];
__device__ float g_w[NK];
__device__ int   g_slot[NK];
__device__ int   g_slot_token[E_NUM * CAP];
__device__ int   g_counts[E_NUM];
__device__ int   g_kept[E_NUM];
__device__ float g_prob_part[ROUTE_BLOCKS * E_NUM];

// ---------------- PTX helpers ----------------
__device__ __forceinline__ uint32_t smem_u32(const void* p) {
    uint32_t a;
    asm("{ .reg .u64 t; cvta.to.shared.u64 t, %1; cvt.u32.u64 %0, t; }" : "=r"(a) : "l"(p));
    return a;
}

#define CPA16(dst, src) \
    asm volatile("cp.async.cg.shared.global [%0], [%1], 16;" :: "r"(dst), "l"(src) : "memory")

#define LDSM4(r, addr) \
    asm volatile("ldmatrix.sync.aligned.m8n8.x4.shared.b16 {%0,%1,%2,%3}, [%4];" \
        : "=r"((r)[0]), "=r"((r)[1]), "=r"((r)[2]), "=r"((r)[3]) : "r"(addr))

#define MMA_F16(d, a, bb) \
    asm volatile("mma.sync.aligned.m16n8k16.row.col.f32.f16.f16.f32 " \
        "{%0,%1,%2,%3}, {%4,%5,%6,%7}, {%8,%9}, {%0,%1,%2,%3};" \
        : "+f"((d)[0]), "+f"((d)[1]), "+f"((d)[2]), "+f"((d)[3]) \
        : "r"((a)[0]), "r"((a)[1]), "r"((a)[2]), "r"((a)[3]), \
          "r"((bb)[0]), "r"((bb)[1]))

// ============================================================
// 0) fp32 -> fp16 convert: all four tensors, one launch
// ============================================================
__global__ __launch_bounds__(256) void conv_all_kernel(const float4* __restrict__ x,
                                                       const float4* __restrict__ w1,
                                                       const float4* __restrict__ wg,
                                                       const float4* __restrict__ w2,
                                                       int n4)
{
    int seg = blockIdx.x >> 11;          // 0..3
    int b   = blockIdx.x & 2047;
    const float4* in;
    __half* dst;
    switch (seg) {
        case 0: in = x;  dst = g_xh;  break;
        case 1: in = w1; dst = g_w1h; break;
        case 2: in = wg; dst = g_wgh; break;
        default: in = w2; dst = g_w2h; break;
    }
    uint2* d4 = (uint2*)dst;
    for (int i = b * blockDim.x + threadIdx.x; i < n4; i += 2048 * blockDim.x) {
        float4 v = in[i];
        __half2 h01 = __halves2half2(__float2half_rn(v.x), __float2half_rn(v.y));
        __half2 h23 = __halves2half2(__float2half_rn(v.z), __float2half_rn(v.w));
        uint2 o;
        o.x = *reinterpret_cast<uint32_t*>(&h01);
        o.y = *reinterpret_cast<uint32_t*>(&h23);
        d4[i] = o;
    }
}

// ============================================================
// 1) routing
// ============================================================
__global__ __launch_bounds__(256) void route_kernel(const float* __restrict__ x,
                                                    const float* __restrict__ gate_w)
{
    __shared__ float sg[E_NUM * IN_D];
    __shared__ float pp[8][E_NUM];
    for (int i = threadIdx.x; i < E_NUM * IN_D; i += blockDim.x) sg[i] = gate_w[i];
    __syncthreads();

    int w = threadIdx.x >> 5, lane = threadIdx.x & 31;
    int t = blockIdx.x * 8 + w;
    const float* xr = x + (size_t)t * IN_D;
    float acc[E_NUM];
#pragma unroll
    for (int e = 0; e < E_NUM; e++) acc[e] = 0.f;
    for (int j = 0; j < IN_D / 32; j++) {
        float xv = xr[lane + j * 32];
#pragma unroll
        for (int e = 0; e < E_NUM; e++) acc[e] += xv * sg[e * IN_D + lane + j * 32];
    }
#pragma unroll
    for (int off = 16; off > 0; off >>= 1)
#pragma unroll
        for (int e = 0; e < E_NUM; e++) acc[e] += __shfl_down_sync(0xffffffffu, acc[e], off);

    if (lane == 0) {
        float m = acc[0];
#pragma unroll
        for (int e = 1; e < E_NUM; e++) m = fmaxf(m, acc[e]);
        float p[E_NUM], s = 0.f;
#pragma unroll
        for (int e = 0; e < E_NUM; e++) { p[e] = expf(acc[e] - m); s += p[e]; }
        float inv = 1.f / s;
#pragma unroll
        for (int e = 0; e < E_NUM; e++) p[e] *= inv;
        int e1 = 0;
#pragma unroll
        for (int e = 1; e < E_NUM; e++) if (p[e] > p[e1]) e1 = e;
        int e2 = (e1 == 0) ? 1 : 0;
#pragma unroll
        for (int e = 0; e < E_NUM; e++) if (e != e1 && p[e] > p[e2]) e2 = e;
        float denom = p[e1] + p[e2] + 1e-9f;
        g_exp[2 * t] = e1; g_exp[2 * t + 1] = e2;
        g_w[2 * t] = p[e1] / denom; g_w[2 * t + 1] = p[e2] / denom;
#pragma unroll
        for (int e = 0; e < E_NUM; e++) pp[w][e] = p[e];
    }
    __syncthreads();
    if (threadIdx.x < E_NUM) {
        float s = 0.f;
        for (int ww = 0; ww < 8; ww++) s += pp[ww][threadIdx.x];
        g_prob_part[blockIdx.x * E_NUM + threadIdx.x] = s;
    }
}

// ============================================================
// 2) dispatch
// ============================================================
__global__ __launch_bounds__(1024) void dispatch_kernel()
{
    __shared__ int sc[1024 * E_NUM];
    int tid = threadIdx.x, base = tid * 32;
    int h[E_NUM];
#pragma unroll
    for (int e = 0; e < E_NUM; e++) h[e] = 0;
    for (int i = 0; i < 32; i++) h[g_exp[base + i]]++;
#pragma unroll
    for (int e = 0; e < E_NUM; e++) sc[tid * E_NUM + e] = h[e];
    __syncthreads();
    for (int off = 1; off < 1024; off <<= 1) {
        int v[E_NUM];
        if (tid >= off)
#pragma unroll
            for (int e = 0; e < E_NUM; e++) v[e] = sc[(tid - off) * E_NUM + e];
        __syncthreads();
        if (tid >= off)
#pragma unroll
            for (int e = 0; e < E_NUM; e++) sc[tid * E_NUM + e] += v[e];
        __syncthreads();
    }
    int basec[E_NUM];
#pragma unroll
    for (int e = 0; e < E_NUM; e++) basec[e] = sc[tid * E_NUM + e] - h[e];
    if (tid == 1023)
#pragma unroll
        for (int e = 0; e < E_NUM; e++) {
            int c = sc[tid * E_NUM + e];
            g_counts[e] = c;
            g_kept[e] = (c < CAP) ? c : CAP;
        }
    for (int i = 0; i < 32; i++) {
        int idx = base + i;
        int e = g_exp[idx];
        int pos = basec[e]++;
        if (pos < CAP) {
            int s = e * CAP + pos;
            g_slot[idx] = s;
            g_slot_token[s] = idx >> 1;
        } else g_slot[idx] = -1;
    }
}

// ============================================================
// 3) loss (parallel): 256 threads; thread = (chunk, expert);
//    32 chunks x 64 blocks each; deterministic tree combine
// ============================================================
__global__ __launch_bounds__(256) void loss_kernel(float* out_loss)
{
    __shared__ float ps[32][E_NUM];
    int tid = threadIdx.x;
    int e = tid & 7, chunk = tid >> 3;           // 32 chunks
    float s = 0.f;
    for (int b = chunk * 64; b < (chunk + 1) * 64; b++)
        s += g_prob_part[b * E_NUM + e];
    ps[chunk][e] = s;
    __syncthreads();
    // tree over chunks (deterministic)
    for (int off = 16; off > 0; off >>= 1) {
        if (chunk < off) ps[chunk][e] += ps[chunk + off][e];
        __syncthreads();
    }
    if (tid == 0 && out_loss) {
        float tot = 0.f;
#pragma unroll
        for (int ee = 0; ee < E_NUM; ee++) {
            float p = ps[0][ee] / (float)NTOK;
            float f = (float)g_counts[ee] / (float)NK;
            tot += p * f;
        }
        *out_loss = (float)E_NUM * tot;
    }
}

// ============================================================
// GEMM tiling: 128x128 tile, BK=32, 8 warps (64x32 warp tile)
// smem rows padded to 80B; single-barrier depth-3 pipeline, 4 slots
// ============================================================
#define LDSROW 80
#define CSZ    (128 * LDSROW)   // 10240 B per component tile

// ============================================================
// 4) GEMM1: h = silu(Xg.fc1^T) * (Xg.gating^T), K=1024
// ============================================================
__global__ __launch_bounds__(256, 1) void gemm1_mma()
{
    extern __shared__ char smem[];
    int e = blockIdx.z;
    int kept = g_kept[e];
    int m0 = blockIdx.x * 128;
    if (m0 >= kept) return;
    int n0 = blockIdx.y * 128;

    uint32_t sb = smem_u32(smem);
    int tid = threadIdx.x, lane = tid & 31, wid = tid >> 5;
    int wm = wid & 1, wn = wid >> 1;

    const __half* gsrc[6];
    uint32_t sdst[6];
#pragma unroll
    for (int ci = 0; ci < 2; ci++) {
        int c = tid + ci * 256;
        int row = c >> 2, kc = c & 3;
        int tok = g_slot_token[e * CAP + m0 + row] & (NTOK - 1);
        size_t ar = (size_t)tok * IN_D + kc * 8;
        size_t br = ((size_t)e * HD + n0 + row) * IN_D + kc * 8;
        gsrc[ci * 3 + 0] = g_xh + ar;
        gsrc[ci * 3 + 1] = g_w1h + br;
        gsrc[ci * 3 + 2] = g_wgh + br;
        uint32_t sd = sb + row * LDSROW + kc * 16;
#pragma unroll
        for (int comp = 0; comp < 3; comp++) sdst[ci * 3 + comp] = sd + comp * CSZ;
    }

    const int STG = 3 * CSZ;   // 30720 per slot, 4 slots
    auto load_stage = [&](int slab, int st) {
        int ko = slab * 32;
        uint32_t so = st * STG;
#pragma unroll
        for (int i = 0; i < 6; i++) CPA16(sdst[i] + so, gsrc[i] + ko);
        asm volatile("cp.async.commit_group;" ::: "memory");
    };
    load_stage(0, 0);
    load_stage(1, 1);
    load_stage(2, 2);

    uint32_t a_off[4], b_off[2];
#pragma unroll
    for (int mi = 0; mi < 4; mi++)
        a_off[mi] = (wm * 64 + mi * 16 + (lane & 15)) * LDSROW + (lane >> 4) * 16;
#pragma unroll
    for (int ni = 0; ni < 2; ni++)
        b_off[ni] = (wn * 32 + ni * 16 + (lane & 7) + ((lane >> 4) << 3)) * LDSROW
                    + ((lane >> 3) & 1) * 16;

    float acc1[4][4][4], acc2[4][4][4];
#pragma unroll
    for (int mi = 0; mi < 4; mi++)
#pragma unroll
        for (int nj = 0; nj < 4; nj++)
#pragma unroll
            for (int q = 0; q < 4; q++) { acc1[mi][nj][q] = 0.f; acc2[mi][nj][q] = 0.f; }

    for (int s = 0; s < 32; s++) {
        int st = s & 3;
        if (s < 29) asm volatile("cp.async.wait_group 2;" ::: "memory");
        else        asm volatile("cp.async.wait_group 0;" ::: "memory");
        __syncthreads();
        if (s < 29) load_stage(s + 3, (s + 3) & 3);
        uint32_t base = sb + st * STG;
#pragma unroll
        for (int ks = 0; ks < 2; ks++) {
            uint32_t kb = ks * 32;
            uint32_t Ah[4][4], B1[2][4], B2[2][4];
#pragma unroll
            for (int mi = 0; mi < 4; mi++) LDSM4(Ah[mi], base + a_off[mi] + kb);
#pragma unroll
            for (int ni = 0; ni < 2; ni++) LDSM4(B1[ni], base + CSZ + b_off[ni] + kb);
#pragma unroll
            for (int ni = 0; ni < 2; ni++) LDSM4(B2[ni], base + 2 * CSZ + b_off[ni] + kb);
#pragma unroll
            for (int mi = 0; mi < 4; mi++)
#pragma unroll
                for (int ni = 0; ni < 2; ni++)
#pragma unroll
                    for (int hh = 0; hh < 2; hh++) {
                        int nj = ni * 2 + hh;
                        MMA_F16(acc1[mi][nj], Ah[mi], B1[ni] + hh * 2);
                        MMA_F16(acc2[mi][nj], Ah[mi], B2[ni] + hh * 2);
                    }
        }
    }

    // SwiGLU epilogue -> fp16 h
#pragma unroll
    for (int mi = 0; mi < 4; mi++) {
        int rbase = m0 + wm * 64 + mi * 16 + (lane >> 2);
#pragma unroll
        for (int rr = 0; rr < 2; rr++) {
            int r = rbase + rr * 8;
            if (r < kept) {
                size_t ro = (size_t)(e * CAP + r) * HD;
#pragma unroll
                for (int nj = 0; nj < 4; nj++) {
                    int col = n0 + wn * 32 + nj * 8 + (lane & 3) * 2;
                    float v0 = acc1[mi][nj][rr * 2 + 0], v1 = acc1[mi][nj][rr * 2 + 1];
                    float g0 = acc2[mi][nj][rr * 2 + 0], g1 = acc2[mi][nj][rr * 2 + 1];
                    float h0 = v0 / (1.f + __expf(-v0)) * g0;
                    float h1 = v1 / (1.f + __expf(-v1)) * g1;
                    *(__half2*)(g_hh + ro + col) =
                        __halves2half2(__float2half_rn(h0), __float2half_rn(h1));
                }
            }
        }
    }
}

// ============================================================
// 5) GEMM2: out = H . fc2^T, K=2048; 2 CTAs/SM
// ============================================================
__global__ __launch_bounds__(256, 2) void gemm2_mma()
{
    extern __shared__ char smem[];
    int e = blockIdx.z;
    int kept = g_kept[e];
    int m0 = blockIdx.x * 128;
    if (m0 >= kept) return;
    int n0 = blockIdx.y * 128;

    uint32_t sb = smem_u32(smem);
    int tid = threadIdx.x, lane = tid & 31, wid = tid >> 5;
    int wm = wid & 1, wn = wid >> 1;

    const __half* gsrc[4];
    uint32_t sdst[4];
#pragma unroll
    for (int ci = 0; ci < 2; ci++) {
        int c = tid + ci * 256;
        int row = c >> 2, kc = c & 3;
        size_t ar = (size_t)(e * CAP + m0 + row) * HD + kc * 8;
        size_t br = ((size_t)e * IN_D + n0 + row) * HD + kc * 8;
        gsrc[ci * 2 + 0] = g_hh + ar;
        gsrc[ci * 2 + 1] = g_w2h + br;
        uint32_t sd = sb + row * LDSROW + kc * 16;
#pragma unroll
        for (int comp = 0; comp < 2; comp++) sdst[ci * 2 + comp] = sd + comp * CSZ;
    }

    const int STG = 2 * CSZ;   // 20480 per slot, 4 slots
    auto load_stage = [&](int slab, int st) {
        int ko = slab * 32;
        uint32_t so = st * STG;
#pragma unroll
        for (int i = 0; i < 4; i++) CPA16(sdst[i] + so, gsrc[i] + ko);
        asm volatile("cp.async.commit_group;" ::: "memory");
    };
    load_stage(0, 0);
    load_stage(1, 1);
    load_stage(2, 2);

    uint32_t a_off[4], b_off[2];
#pragma unroll
    for (int mi = 0; mi < 4; mi++)
        a_off[mi] = (wm * 64 + mi * 16 + (lane & 15)) * LDSROW + (lane >> 4) * 16;
#pragma unroll
    for (int ni = 0; ni < 2; ni++)
        b_off[ni] = (wn * 32 + ni * 16 + (lane & 7) + ((lane >> 4) << 3)) * LDSROW
                    + ((lane >> 3) & 1) * 16;

    float acc[4][4][4];
#pragma unroll
    for (int mi = 0; mi < 4; mi++)
#pragma unroll
        for (int nj = 0; nj < 4; nj++)
#pragma unroll
            for (int q = 0; q < 4; q++) acc[mi][nj][q] = 0.f;

    for (int s = 0; s < 64; s++) {
        int st = s & 3;
        if (s < 61) asm volatile("cp.async.wait_group 2;" ::: "memory");
        else        asm volatile("cp.async.wait_group 0;" ::: "memory");
        __syncthreads();
        if (s < 61) load_stage(s + 3, (s + 3) & 3);
        uint32_t base = sb + st * STG;
#pragma unroll
        for (int ks = 0; ks < 2; ks++) {
            uint32_t kb = ks * 32;
            uint32_t Ah[4][4], B[2][4];
#pragma unroll
            for (int mi = 0; mi < 4; mi++) LDSM4(Ah[mi], base + a_off[mi] + kb);
#pragma unroll
            for (int ni = 0; ni < 2; ni++) LDSM4(B[ni], base + CSZ + b_off[ni] + kb);
#pragma unroll
            for (int mi = 0; mi < 4; mi++)
#pragma unroll
                for (int ni = 0; ni < 2; ni++)
#pragma unroll
                    for (int hh = 0; hh < 2; hh++)
                        MMA_F16(acc[mi][ni * 2 + hh], Ah[mi], B[ni] + hh * 2);
        }
    }

#pragma unroll
    for (int mi = 0; mi < 4; mi++) {
        int rbase = m0 + wm * 64 + mi * 16 + (lane >> 2);
#pragma unroll
        for (int rr = 0; rr < 2; rr++) {
            int r = rbase + rr * 8;
            if (r < kept) {
                size_t ro = (size_t)(e * CAP + r) * IN_D;
#pragma unroll
                for (int nj = 0; nj < 4; nj++) {
                    int col = n0 + wn * 32 + nj * 8 + (lane & 3) * 2;
                    *(__half2*)(g_buf_out + ro + col) =
                        __halves2half2(__float2half_rn(acc[mi][nj][rr * 2 + 0]),
                                       __float2half_rn(acc[mi][nj][rr * 2 + 1]));
                }
            }
        }
    }
}

// ============================================================
// 6) combine (fp16 buf)
// ============================================================
__global__ __launch_bounds__(256) void combine_kernel(float* __restrict__ out)
{
    int t = blockIdx.x;
    int s1 = g_slot[2 * t];
    int s2 = g_slot[2 * t + 1];
    float w1 = (s1 >= 0) ? g_w[2 * t] : 0.f;
    float w2 = (s2 >= 0) ? g_w[2 * t + 1] : 0.f;
    const uint2* r1 = (s1 >= 0) ? (const uint2*)(g_buf_out + (size_t)s1 * IN_D) : nullptr;
    const uint2* r2 = (s2 >= 0) ? (const uint2*)(g_buf_out + (size_t)s2 * IN_D) : nullptr;

    int d = threadIdx.x;
    float4 v = make_float4(0, 0, 0, 0);
    if (r1) {
        uint2 a = r1[d];
        float2 p = __half22float2(*reinterpret_cast<__half2*>(&a.x));
        float2 q = __half22float2(*reinterpret_cast<__half2*>(&a.y));
        v.x += w1 * p.x; v.y += w1 * p.y; v.z += w1 * q.x; v.w += w1 * q.y;
    }
    if (r2) {
        uint2 a = r2[d];
        float2 p = __half22float2(*reinterpret_cast<__half2*>(&a.x));
        float2 q = __half22float2(*reinterpret_cast<__half2*>(&a.y));
        v.x += w2 * p.x; v.y += w2 * p.y; v.z += w2 * q.x; v.w += w2 * q.y;
    }
    ((float4*)(out + (size_t)t * IN_D))[d] = v;
}

// ============================================================
extern "C" void kernel_launch(void* const* d_in, const int* in_sizes, int n_in,
                              void* d_out, int out_size)
{
    const float* x      = (const float*)d_in[0];
    const float* gate_w = (const float*)d_in[1];
    const float* fc1_w  = (const float*)d_in[2];
    const float* gating = (const float*)d_in[3];
    const float* fc2_w  = (const float*)d_in[4];
    float* out = (float*)d_out;
    float* loss_ptr = (out_size > NTOK * IN_D) ? out + (size_t)NTOK * IN_D : nullptr;

    const int smem1 = 4 * 3 * CSZ;   // 122880
    const int smem2 = 4 * 2 * CSZ;   // 81920  (2 CTAs/SM)
    cudaFuncSetAttribute(gemm1_mma, cudaFuncAttributeMaxDynamicSharedMemorySize, smem1);
    cudaFuncSetAttribute(gemm2_mma, cudaFuncAttributeMaxDynamicSharedMemorySize, smem2);

    const int n4 = NTOK * IN_D / 4;
    conv_all_kernel<<<8192, 256>>>((const float4*)x, (const float4*)fc1_w,
                                   (const float4*)gating, (const float4*)fc2_w, n4);

    route_kernel<<<ROUTE_BLOCKS, 256>>>(x, gate_w);
    dispatch_kernel<<<1, 1024>>>();
    loss_kernel<<<1, 256>>>(loss_ptr);
    gemm1_mma<<<dim3(CAP / 128, HD / 128, E_NUM), 256, smem1>>>();
    gemm2_mma<<<dim3(CAP / 128, IN_D / 128, E_NUM), 256, smem2>>>();
    combine_kernel<<<NTOK, 256>>>(out);
}

// round 13
// speedup vs baseline: 1.1026x; 1.0057x over previous
#include <cuda_runtime.h>
#include <cuda_bf16.h>
#include <cuda_fp16.h>
#include <cstdint>
#include <math.h>

// ---------------- problem constants ----------------
#define E_NUM      8
#define TOPK       2
#define IN_D       1024
#define HD         2048
#define NTOK       16384
#define NK         32768
#define CAP        5120
#define ROUTE_BLOCKS 2048

// ---------------- device scratch ----------------
__device__ __half g_xh[(size_t)NTOK * IN_D];
__device__ __half g_w1h[(size_t)E_NUM * HD * IN_D];
__device__ __half g_wgh[(size_t)E_NUM * HD * IN_D];
__device__ __half g_w2h[(size_t)E_NUM * IN_D * HD];
__device__ __half g_hh[(size_t)E_NUM * CAP * HD];
__device__ __half g_buf_out[(size_t)E_NUM * CAP * IN_D];
__device__ int   g_exp[NK];
__device__ float g_w[NK];
__device__ int   g_slot[NK];
__device__ int   g_slot_token[E_NUM * CAP];
__device__ int   g_counts[E_NUM];
__device__ int   g_kept[E_NUM];
__device__ float g_prob_part[ROUTE_BLOCKS * E_NUM];

// ---------------- PTX helpers ----------------
__device__ __forceinline__ uint32_t smem_u32(const void* p) {
    uint32_t a;
    asm("{ .reg .u64 t; cvta.to.shared.u64 t, %1; cvt.u32.u64 %0, t; }" : "=r"(a) : "l"(p));
    return a;
}

#define CPA16(dst, src) \
    asm volatile("cp.async.cg.shared.global [%0], [%1], 16;" :: "r"(dst), "l"(src) : "memory")

#define LDSM4(r, addr) \
    asm volatile("ldmatrix.sync.aligned.m8n8.x4.shared.b16 {%0,%1,%2,%3}, [%4];" \
        : "=r"((r)[0]), "=r"((r)[1]), "=r"((r)[2]), "=r"((r)[3]) : "r"(addr))

#define MMA_F16(d, a, bb) \
    asm volatile("mma.sync.aligned.m16n8k16.row.col.f32.f16.f16.f32 " \
        "{%0,%1,%2,%3}, {%4,%5,%6,%7}, {%8,%9}, {%0,%1,%2,%3};" \
        : "+f"((d)[0]), "+f"((d)[1]), "+f"((d)[2]), "+f"((d)[3]) \
        : "r"((a)[0]), "r"((a)[1]), "r"((a)[2]), "r"((a)[3]), \
          "r"((bb)[0]), "r"((bb)[1]))

__device__ __forceinline__ uint32_t pack_h2(float a, float b) {
    __half2 h = __halves2half2(__float2half_rn(a), __float2half_rn(b));
    return *reinterpret_cast<uint32_t*>(&h);
}

// ============================================================
// 0+1) prep: routing (blocks 0..2047) + fp32->fp16 convert
//      (blocks 2048..10239, 4 segments x 2048, 16B stores)
// ============================================================
__global__ __launch_bounds__(256) void prep_kernel(const float* __restrict__ x,
                                                   const float* __restrict__ gate_w,
                                                   const float4* __restrict__ x4,
                                                   const float4* __restrict__ w14,
                                                   const float4* __restrict__ wg4,
                                                   const float4* __restrict__ w24,
                                                   int n8)
{
    __shared__ float sg[E_NUM * IN_D];   // 32KB (route only)
    __shared__ float pp[8][E_NUM];

    if (blockIdx.x < ROUTE_BLOCKS) {
        // ---- routing ----
        for (int i = threadIdx.x; i < E_NUM * IN_D; i += blockDim.x) sg[i] = gate_w[i];
        __syncthreads();

        int w = threadIdx.x >> 5, lane = threadIdx.x & 31;
        int t = blockIdx.x * 8 + w;
        const float* xr = x + (size_t)t * IN_D;
        float acc[E_NUM];
#pragma unroll
        for (int e = 0; e < E_NUM; e++) acc[e] = 0.f;
        for (int j = 0; j < IN_D / 32; j++) {
            float xv = xr[lane + j * 32];
#pragma unroll
            for (int e = 0; e < E_NUM; e++) acc[e] += xv * sg[e * IN_D + lane + j * 32];
        }
#pragma unroll
        for (int off = 16; off > 0; off >>= 1)
#pragma unroll
            for (int e = 0; e < E_NUM; e++) acc[e] += __shfl_down_sync(0xffffffffu, acc[e], off);

        if (lane == 0) {
            float m = acc[0];
#pragma unroll
            for (int e = 1; e < E_NUM; e++) m = fmaxf(m, acc[e]);
            float p[E_NUM], s = 0.f;
#pragma unroll
            for (int e = 0; e < E_NUM; e++) { p[e] = expf(acc[e] - m); s += p[e]; }
            float inv = 1.f / s;
#pragma unroll
            for (int e = 0; e < E_NUM; e++) p[e] *= inv;
            int e1 = 0;
#pragma unroll
            for (int e = 1; e < E_NUM; e++) if (p[e] > p[e1]) e1 = e;
            int e2 = (e1 == 0) ? 1 : 0;
#pragma unroll
            for (int e = 0; e < E_NUM; e++) if (e != e1 && p[e] > p[e2]) e2 = e;
            float denom = p[e1] + p[e2] + 1e-9f;
            g_exp[2 * t] = e1; g_exp[2 * t + 1] = e2;
            g_w[2 * t] = p[e1] / denom; g_w[2 * t + 1] = p[e2] / denom;
#pragma unroll
            for (int e = 0; e < E_NUM; e++) pp[w][e] = p[e];
        }
        __syncthreads();
        if (threadIdx.x < E_NUM) {
            float s = 0.f;
            for (int ww = 0; ww < 8; ww++) s += pp[ww][threadIdx.x];
            g_prob_part[blockIdx.x * E_NUM + threadIdx.x] = s;
        }
        return;
    }

    // ---- convert: 2 float4 in -> 1 uint4 (8 halves) out ----
    int rb  = blockIdx.x - ROUTE_BLOCKS;
    int seg = rb >> 11;          // 0..3
    int b   = rb & 2047;
    const float4* in;
    __half* dst;
    switch (seg) {
        case 0: in = x4;  dst = g_xh;  break;
        case 1: in = w14; dst = g_w1h; break;
        case 2: in = wg4; dst = g_wgh; break;
        default: in = w24; dst = g_w2h; break;
    }
    uint4* d8 = (uint4*)dst;
    for (int i = b * blockDim.x + threadIdx.x; i < n8; i += 2048 * blockDim.x) {
        float4 a = in[2 * i], c = in[2 * i + 1];
        uint4 o;
        o.x = pack_h2(a.x, a.y);
        o.y = pack_h2(a.z, a.w);
        o.z = pack_h2(c.x, c.y);
        o.w = pack_h2(c.z, c.w);
        d8[i] = o;
    }
}

// ============================================================
// 2) dispatch + loss (fused tail)
// ============================================================
__global__ __launch_bounds__(1024) void dispatch_kernel(float* out_loss)
{
    __shared__ int sc[1024 * E_NUM];   // 32KB
    __shared__ float ps[32][E_NUM];
    int tid = threadIdx.x, base = tid * 32;
    int h[E_NUM];
#pragma unroll
    for (int e = 0; e < E_NUM; e++) h[e] = 0;
    for (int i = 0; i < 32; i++) h[g_exp[base + i]]++;
#pragma unroll
    for (int e = 0; e < E_NUM; e++) sc[tid * E_NUM + e] = h[e];
    __syncthreads();
    for (int off = 1; off < 1024; off <<= 1) {
        int v[E_NUM];
        if (tid >= off)
#pragma unroll
            for (int e = 0; e < E_NUM; e++) v[e] = sc[(tid - off) * E_NUM + e];
        __syncthreads();
        if (tid >= off)
#pragma unroll
            for (int e = 0; e < E_NUM; e++) sc[tid * E_NUM + e] += v[e];
        __syncthreads();
    }
    int basec[E_NUM];
#pragma unroll
    for (int e = 0; e < E_NUM; e++) basec[e] = sc[tid * E_NUM + e] - h[e];
    if (tid == 1023)
#pragma unroll
        for (int e = 0; e < E_NUM; e++) {
            int c = sc[tid * E_NUM + e];
            g_counts[e] = c;
            g_kept[e] = (c < CAP) ? c : CAP;
        }
    for (int i = 0; i < 32; i++) {
        int idx = base + i;
        int e = g_exp[idx];
        int pos = basec[e]++;
        if (pos < CAP) {
            int s = e * CAP + pos;
            g_slot[idx] = s;
            g_slot_token[s] = idx >> 1;
        } else g_slot[idx] = -1;
    }

    // ---- loss tail (threads 0..255; same summation order as before) ----
    int le = tid & 7, chunk = tid >> 3;
    if (tid < 256) {
        float s = 0.f;
        for (int b2 = chunk * 64; b2 < (chunk + 1) * 64; b2++)
            s += g_prob_part[b2 * E_NUM + le];
        ps[chunk][le] = s;
    }
    __syncthreads();
    for (int off = 16; off > 0; off >>= 1) {
        if (tid < 256 && chunk < off) ps[chunk][le] += ps[chunk + off][le];
        __syncthreads();
    }
    if (tid == 0 && out_loss) {
        float tot = 0.f;
#pragma unroll
        for (int ee = 0; ee < E_NUM; ee++) {
            float p = ps[0][ee] / (float)NTOK;
            float f = (float)sc[1023 * E_NUM + ee] / (float)NK;
            tot += p * f;
        }
        *out_loss = (float)E_NUM * tot;
    }
}

// ============================================================
// GEMM tiling: 128x128 tile, BK=32, 8 warps (64x32 warp tile)
// smem rows padded to 80B; single-barrier depth-3 pipeline, 4 slots
// ============================================================
#define LDSROW 80
#define CSZ    (128 * LDSROW)   // 10240 B per component tile

// ============================================================
// 4) GEMM1: h = silu(Xg.fc1^T) * (Xg.gating^T), K=1024
// ============================================================
__global__ __launch_bounds__(256, 1) void gemm1_mma()
{
    extern __shared__ char smem[];
    int e = blockIdx.z;
    int kept = g_kept[e];
    int m0 = blockIdx.x * 128;
    if (m0 >= kept) return;
    int n0 = blockIdx.y * 128;

    uint32_t sb = smem_u32(smem);
    int tid = threadIdx.x, lane = tid & 31, wid = tid >> 5;
    int wm = wid & 1, wn = wid >> 1;

    const __half* gsrc[6];
    uint32_t sdst[6];
#pragma unroll
    for (int ci = 0; ci < 2; ci++) {
        int c = tid + ci * 256;
        int row = c >> 2, kc = c & 3;
        int tok = g_slot_token[e * CAP + m0 + row] & (NTOK - 1);
        size_t ar = (size_t)tok * IN_D + kc * 8;
        size_t br = ((size_t)e * HD + n0 + row) * IN_D + kc * 8;
        gsrc[ci * 3 + 0] = g_xh + ar;
        gsrc[ci * 3 + 1] = g_w1h + br;
        gsrc[ci * 3 + 2] = g_wgh + br;
        uint32_t sd = sb + row * LDSROW + kc * 16;
#pragma unroll
        for (int comp = 0; comp < 3; comp++) sdst[ci * 3 + comp] = sd + comp * CSZ;
    }

    const int STG = 3 * CSZ;   // 30720 per slot, 4 slots
    auto load_stage = [&](int slab, int st) {
        int ko = slab * 32;
        uint32_t so = st * STG;
#pragma unroll
        for (int i = 0; i < 6; i++) CPA16(sdst[i] + so, gsrc[i] + ko);
        asm volatile("cp.async.commit_group;" ::: "memory");
    };
    load_stage(0, 0);
    load_stage(1, 1);
    load_stage(2, 2);

    uint32_t a_off[4], b_off[2];
#pragma unroll
    for (int mi = 0; mi < 4; mi++)
        a_off[mi] = (wm * 64 + mi * 16 + (lane & 15)) * LDSROW + (lane >> 4) * 16;
#pragma unroll
    for (int ni = 0; ni < 2; ni++)
        b_off[ni] = (wn * 32 + ni * 16 + (lane & 7) + ((lane >> 4) << 3)) * LDSROW
                    + ((lane >> 3) & 1) * 16;

    float acc1[4][4][4], acc2[4][4][4];
#pragma unroll
    for (int mi = 0; mi < 4; mi++)
#pragma unroll
        for (int nj = 0; nj < 4; nj++)
#pragma unroll
            for (int q = 0; q < 4; q++) { acc1[mi][nj][q] = 0.f; acc2[mi][nj][q] = 0.f; }

    for (int s = 0; s < 32; s++) {
        int st = s & 3;
        if (s < 29) asm volatile("cp.async.wait_group 2;" ::: "memory");
        else        asm volatile("cp.async.wait_group 0;" ::: "memory");
        __syncthreads();
        if (s < 29) load_stage(s + 3, (s + 3) & 3);
        uint32_t base = sb + st * STG;
#pragma unroll
        for (int ks = 0; ks < 2; ks++) {
            uint32_t kb = ks * 32;
            uint32_t Ah[4][4], B1[2][4], B2[2][4];
#pragma unroll
            for (int mi = 0; mi < 4; mi++) LDSM4(Ah[mi], base + a_off[mi] + kb);
#pragma unroll
            for (int ni = 0; ni < 2; ni++) LDSM4(B1[ni], base + CSZ + b_off[ni] + kb);
#pragma unroll
            for (int ni = 0; ni < 2; ni++) LDSM4(B2[ni], base + 2 * CSZ + b_off[ni] + kb);
#pragma unroll
            for (int mi = 0; mi < 4; mi++)
#pragma unroll
                for (int ni = 0; ni < 2; ni++)
#pragma unroll
                    for (int hh = 0; hh < 2; hh++) {
                        int nj = ni * 2 + hh;
                        MMA_F16(acc1[mi][nj], Ah[mi], B1[ni] + hh * 2);
                        MMA_F16(acc2[mi][nj], Ah[mi], B2[ni] + hh * 2);
                    }
        }
    }

    // SwiGLU epilogue -> fp16 h
#pragma unroll
    for (int mi = 0; mi < 4; mi++) {
        int rbase = m0 + wm * 64 + mi * 16 + (lane >> 2);
#pragma unroll
        for (int rr = 0; rr < 2; rr++) {
            int r = rbase + rr * 8;
            if (r < kept) {
                size_t ro = (size_t)(e * CAP + r) * HD;
#pragma unroll
                for (int nj = 0; nj < 4; nj++) {
                    int col = n0 + wn * 32 + nj * 8 + (lane & 3) * 2;
                    float v0 = acc1[mi][nj][rr * 2 + 0], v1 = acc1[mi][nj][rr * 2 + 1];
                    float g0 = acc2[mi][nj][rr * 2 + 0], g1 = acc2[mi][nj][rr * 2 + 1];
                    float h0 = v0 / (1.f + __expf(-v0)) * g0;
                    float h1 = v1 / (1.f + __expf(-v1)) * g1;
                    *(__half2*)(g_hh + ro + col) =
                        __halves2half2(__float2half_rn(h0), __float2half_rn(h1));
                }
            }
        }
    }
}

// ============================================================
// 5) GEMM2: out = H . fc2^T, K=2048; 2 CTAs/SM
// ============================================================
__global__ __launch_bounds__(256, 2) void gemm2_mma()
{
    extern __shared__ char smem[];
    int e = blockIdx.z;
    int kept = g_kept[e];
    int m0 = blockIdx.x * 128;
    if (m0 >= kept) return;
    int n0 = blockIdx.y * 128;

    uint32_t sb = smem_u32(smem);
    int tid = threadIdx.x, lane = tid & 31, wid = tid >> 5;
    int wm = wid & 1, wn = wid >> 1;

    const __half* gsrc[4];
    uint32_t sdst[4];
#pragma unroll
    for (int ci = 0; ci < 2; ci++) {
        int c = tid + ci * 256;
        int row = c >> 2, kc = c & 3;
        size_t ar = (size_t)(e * CAP + m0 + row) * HD + kc * 8;
        size_t br = ((size_t)e * IN_D + n0 + row) * HD + kc * 8;
        gsrc[ci * 2 + 0] = g_hh + ar;
        gsrc[ci * 2 + 1] = g_w2h + br;
        uint32_t sd = sb + row * LDSROW + kc * 16;
#pragma unroll
        for (int comp = 0; comp < 2; comp++) sdst[ci * 2 + comp] = sd + comp * CSZ;
    }

    const int STG = 2 * CSZ;   // 20480 per slot, 4 slots
    auto load_stage = [&](int slab, int st) {
        int ko = slab * 32;
        uint32_t so = st * STG;
#pragma unroll
        for (int i = 0; i < 4; i++) CPA16(sdst[i] + so, gsrc[i] + ko);
        asm volatile("cp.async.commit_group;" ::: "memory");
    };
    load_stage(0, 0);
    load_stage(1, 1);
    load_stage(2, 2);

    uint32_t a_off[4], b_off[2];
#pragma unroll
    for (int mi = 0; mi < 4; mi++)
        a_off[mi] = (wm * 64 + mi * 16 + (lane & 15)) * LDSROW + (lane >> 4) * 16;
#pragma unroll
    for (int ni = 0; ni < 2; ni++)
        b_off[ni] = (wn * 32 + ni * 16 + (lane & 7) + ((lane >> 4) << 3)) * LDSROW
                    + ((lane >> 3) & 1) * 16;

    float acc[4][4][4];
#pragma unroll
    for (int mi = 0; mi < 4; mi++)
#pragma unroll
        for (int nj = 0; nj < 4; nj++)
#pragma unroll
            for (int q = 0; q < 4; q++) acc[mi][nj][q] = 0.f;

    for (int s = 0; s < 64; s++) {
        int st = s & 3;
        if (s < 61) asm volatile("cp.async.wait_group 2;" ::: "memory");
        else        asm volatile("cp.async.wait_group 0;" ::: "memory");
        __syncthreads();
        if (s < 61) load_stage(s + 3, (s + 3) & 3);
        uint32_t base = sb + st * STG;
#pragma unroll
        for (int ks = 0; ks < 2; ks++) {
            uint32_t kb = ks * 32;
            uint32_t Ah[4][4], B[2][4];
#pragma unroll
            for (int mi = 0; mi < 4; mi++) LDSM4(Ah[mi], base + a_off[mi] + kb);
#pragma unroll
            for (int ni = 0; ni < 2; ni++) LDSM4(B[ni], base + CSZ + b_off[ni] + kb);
#pragma unroll
            for (int mi = 0; mi < 4; mi++)
#pragma unroll
                for (int ni = 0; ni < 2; ni++)
#pragma unroll
                    for (int hh = 0; hh < 2; hh++)
                        MMA_F16(acc[mi][ni * 2 + hh], Ah[mi], B[ni] + hh * 2);
        }
    }

#pragma unroll
    for (int mi = 0; mi < 4; mi++) {
        int rbase = m0 + wm * 64 + mi * 16 + (lane >> 2);
#pragma unroll
        for (int rr = 0; rr < 2; rr++) {
            int r = rbase + rr * 8;
            if (r < kept) {
                size_t ro = (size_t)(e * CAP + r) * IN_D;
#pragma unroll
                for (int nj = 0; nj < 4; nj++) {
                    int col = n0 + wn * 32 + nj * 8 + (lane & 3) * 2;
                    *(__half2*)(g_buf_out + ro + col) =
                        __halves2half2(__float2half_rn(acc[mi][nj][rr * 2 + 0]),
                                       __float2half_rn(acc[mi][nj][rr * 2 + 1]));
                }
            }
        }
    }
}

// ============================================================
// 6) combine (fp16 buf)
// ============================================================
__global__ __launch_bounds__(256) void combine_kernel(float* __restrict__ out)
{
    int t = blockIdx.x;
    int s1 = g_slot[2 * t];
    int s2 = g_slot[2 * t + 1];
    float w1 = (s1 >= 0) ? g_w[2 * t] : 0.f;
    float w2 = (s2 >= 0) ? g_w[2 * t + 1] : 0.f;
    const uint2* r1 = (s1 >= 0) ? (const uint2*)(g_buf_out + (size_t)s1 * IN_D) : nullptr;
    const uint2* r2 = (s2 >= 0) ? (const uint2*)(g_buf_out + (size_t)s2 * IN_D) : nullptr;

    int d = threadIdx.x;
    float4 v = make_float4(0, 0, 0, 0);
    if (r1) {
        uint2 a = r1[d];
        float2 p = __half22float2(*reinterpret_cast<__half2*>(&a.x));
        float2 q = __half22float2(*reinterpret_cast<__half2*>(&a.y));
        v.x += w1 * p.x; v.y += w1 * p.y; v.z += w1 * q.x; v.w += w1 * q.y;
    }
    if (r2) {
        uint2 a = r2[d];
        float2 p = __half22float2(*reinterpret_cast<__half2*>(&a.x));
        float2 q = __half22float2(*reinterpret_cast<__half2*>(&a.y));
        v.x += w2 * p.x; v.y += w2 * p.y; v.z += w2 * q.x; v.w += w2 * q.y;
    }
    ((float4*)(out + (size_t)t * IN_D))[d] = v;
}

// ============================================================
extern "C" void kernel_launch(void* const* d_in, const int* in_sizes, int n_in,
                              void* d_out, int out_size)
{
    const float* x      = (const float*)d_in[0];
    const float* gate_w = (const float*)d_in[1];
    const float* fc1_w  = (const float*)d_in[2];
    const float* gating = (const float*)d_in[3];
    const float* fc2_w  = (const float*)d_in[4];
    float* out = (float*)d_out;
    float* loss_ptr = (out_size > NTOK * IN_D) ? out + (size_t)NTOK * IN_D : nullptr;

    const int smem1 = 4 * 3 * CSZ;   // 122880
    const int smem2 = 4 * 2 * CSZ;   // 81920  (2 CTAs/SM)
    cudaFuncSetAttribute(gemm1_mma, cudaFuncAttributeMaxDynamicSharedMemorySize, smem1);
    cudaFuncSetAttribute(gemm2_mma, cudaFuncAttributeMaxDynamicSharedMemorySize, smem2);

    const int n8 = NTOK * IN_D / 8;   // uint4 outputs per tensor
    prep_kernel<<<ROUTE_BLOCKS + 8192, 256>>>(x, gate_w,
                                              (const float4*)x,
                                              (const float4*)fc1_w,
                                              (const float4*)gating,
                                              (const float4*)fc2_w, n8);

    dispatch_kernel<<<1, 1024>>>(loss_ptr);
    gemm1_mma<<<dim3(CAP / 128, HD / 128, E_NUM), 256, smem1>>>();
    gemm2_mma<<<dim3(CAP / 128, IN_D / 128, E_NUM), 256, smem2>>>();
    combine_kernel<<<NTOK, 256>>>(out);
}

// round 14
// speedup vs baseline: 1.1452x; 1.0387x over previous
#include <cuda_runtime.h>
#include <cuda_bf16.h>
#include <cuda_fp16.h>
#include <cstdint>
#include <math.h>

// ---------------- problem constants ----------------
#define E_NUM      8
#define TOPK       2
#define IN_D       1024
#define HD         2048
#define NTOK       16384
#define NK         32768
#define CAP        5120
#define ROUTE_BLOCKS 2048

// ---------------- device scratch ----------------
__device__ __half g_xh[(size_t)NTOK * IN_D];
__device__ __half g_w1h[(size_t)E_NUM * HD * IN_D];
__device__ __half g_wgh[(size_t)E_NUM * HD * IN_D];
__device__ __half g_w2h[(size_t)E_NUM * IN_D * HD];
__device__ __half g_hh[(size_t)E_NUM * CAP * HD];
__device__ __half g_buf_out[(size_t)E_NUM * CAP * IN_D];
__device__ int   g_exp[NK];
__device__ float g_w[NK];
__device__ int   g_slot[NK];
__device__ int   g_slot_token[E_NUM * CAP];
__device__ int   g_counts[E_NUM];
__device__ int   g_kept[E_NUM];
__device__ float g_prob_part[ROUTE_BLOCKS * E_NUM];

// ---------------- PTX helpers ----------------
__device__ __forceinline__ uint32_t smem_u32(const void* p) {
    uint32_t a;
    asm("{ .reg .u64 t; cvta.to.shared.u64 t, %1; cvt.u32.u64 %0, t; }" : "=r"(a) : "l"(p));
    return a;
}

#define CPA16(dst, src) \
    asm volatile("cp.async.cg.shared.global [%0], [%1], 16;" :: "r"(dst), "l"(src) : "memory")

#define LDSM4(r, addr) \
    asm volatile("ldmatrix.sync.aligned.m8n8.x4.shared.b16 {%0,%1,%2,%3}, [%4];" \
        : "=r"((r)[0]), "=r"((r)[1]), "=r"((r)[2]), "=r"((r)[3]) : "r"(addr))

#define MMA_F16(d, a, bb) \
    asm volatile("mma.sync.aligned.m16n8k16.row.col.f32.f16.f16.f32 " \
        "{%0,%1,%2,%3}, {%4,%5,%6,%7}, {%8,%9}, {%0,%1,%2,%3};" \
        : "+f"((d)[0]), "+f"((d)[1]), "+f"((d)[2]), "+f"((d)[3]) \
        : "r"((a)[0]), "r"((a)[1]), "r"((a)[2]), "r"((a)[3]), \
          "r"((bb)[0]), "r"((bb)[1]))

__device__ __forceinline__ uint32_t pack_h2(float a, float b) {
    __half2 h = __halves2half2(__float2half_rn(a), __float2half_rn(b));
    return *reinterpret_cast<uint32_t*>(&h);
}

// ============================================================
// 0+1) prep: routing (blocks 0..2047) + fp32->fp16 convert
// ============================================================
__global__ __launch_bounds__(256) void prep_kernel(const float* __restrict__ x,
                                                   const float* __restrict__ gate_w,
                                                   const float4* __restrict__ x4,
                                                   const float4* __restrict__ w14,
                                                   const float4* __restrict__ wg4,
                                                   const float4* __restrict__ w24,
                                                   int n8)
{
    __shared__ float sg[E_NUM * IN_D];   // 32KB (route only)
    __shared__ float pp[8][E_NUM];

    if (blockIdx.x < ROUTE_BLOCKS) {
        for (int i = threadIdx.x; i < E_NUM * IN_D; i += blockDim.x) sg[i] = gate_w[i];
        __syncthreads();

        int w = threadIdx.x >> 5, lane = threadIdx.x & 31;
        int t = blockIdx.x * 8 + w;
        const float* xr = x + (size_t)t * IN_D;
        float acc[E_NUM];
#pragma unroll
        for (int e = 0; e < E_NUM; e++) acc[e] = 0.f;
        for (int j = 0; j < IN_D / 32; j++) {
            float xv = xr[lane + j * 32];
#pragma unroll
            for (int e = 0; e < E_NUM; e++) acc[e] += xv * sg[e * IN_D + lane + j * 32];
        }
#pragma unroll
        for (int off = 16; off > 0; off >>= 1)
#pragma unroll
            for (int e = 0; e < E_NUM; e++) acc[e] += __shfl_down_sync(0xffffffffu, acc[e], off);

        if (lane == 0) {
            float m = acc[0];
#pragma unroll
            for (int e = 1; e < E_NUM; e++) m = fmaxf(m, acc[e]);
            float p[E_NUM], s = 0.f;
#pragma unroll
            for (int e = 0; e < E_NUM; e++) { p[e] = expf(acc[e] - m); s += p[e]; }
            float inv = 1.f / s;
#pragma unroll
            for (int e = 0; e < E_NUM; e++) p[e] *= inv;
            int e1 = 0;
#pragma unroll
            for (int e = 1; e < E_NUM; e++) if (p[e] > p[e1]) e1 = e;
            int e2 = (e1 == 0) ? 1 : 0;
#pragma unroll
            for (int e = 0; e < E_NUM; e++) if (e != e1 && p[e] > p[e2]) e2 = e;
            float denom = p[e1] + p[e2] + 1e-9f;
            g_exp[2 * t] = e1; g_exp[2 * t + 1] = e2;
            g_w[2 * t] = p[e1] / denom; g_w[2 * t + 1] = p[e2] / denom;
#pragma unroll
            for (int e = 0; e < E_NUM; e++) pp[w][e] = p[e];
        }
        __syncthreads();
        if (threadIdx.x < E_NUM) {
            float s = 0.f;
            for (int ww = 0; ww < 8; ww++) s += pp[ww][threadIdx.x];
            g_prob_part[blockIdx.x * E_NUM + threadIdx.x] = s;
        }
        return;
    }

    int rb  = blockIdx.x - ROUTE_BLOCKS;
    int seg = rb >> 11;
    int b   = rb & 2047;
    const float4* in;
    __half* dst;
    switch (seg) {
        case 0: in = x4;  dst = g_xh;  break;
        case 1: in = w14; dst = g_w1h; break;
        case 2: in = wg4; dst = g_wgh; break;
        default: in = w24; dst = g_w2h; break;
    }
    uint4* d8 = (uint4*)dst;
    for (int i = b * blockDim.x + threadIdx.x; i < n8; i += 2048 * blockDim.x) {
        float4 a = in[2 * i], c = in[2 * i + 1];
        uint4 o;
        o.x = pack_h2(a.x, a.y);
        o.y = pack_h2(a.z, a.w);
        o.z = pack_h2(c.x, c.y);
        o.w = pack_h2(c.z, c.w);
        d8[i] = o;
    }
}

// ============================================================
// 2) dispatch + loss (fused tail)
// ============================================================
__global__ __launch_bounds__(1024) void dispatch_kernel(float* out_loss)
{
    __shared__ int sc[1024 * E_NUM];
    __shared__ float ps[32][E_NUM];
    int tid = threadIdx.x, base = tid * 32;
    int h[E_NUM];
#pragma unroll
    for (int e = 0; e < E_NUM; e++) h[e] = 0;
    for (int i = 0; i < 32; i++) h[g_exp[base + i]]++;
#pragma unroll
    for (int e = 0; e < E_NUM; e++) sc[tid * E_NUM + e] = h[e];
    __syncthreads();
    for (int off = 1; off < 1024; off <<= 1) {
        int v[E_NUM];
        if (tid >= off)
#pragma unroll
            for (int e = 0; e < E_NUM; e++) v[e] = sc[(tid - off) * E_NUM + e];
        __syncthreads();
        if (tid >= off)
#pragma unroll
            for (int e = 0; e < E_NUM; e++) sc[tid * E_NUM + e] += v[e];
        __syncthreads();
    }
    int basec[E_NUM];
#pragma unroll
    for (int e = 0; e < E_NUM; e++) basec[e] = sc[tid * E_NUM + e] - h[e];
    if (tid == 1023)
#pragma unroll
        for (int e = 0; e < E_NUM; e++) {
            int c = sc[tid * E_NUM + e];
            g_counts[e] = c;
            g_kept[e] = (c < CAP) ? c : CAP;
        }
    for (int i = 0; i < 32; i++) {
        int idx = base + i;
        int e = g_exp[idx];
        int pos = basec[e]++;
        if (pos < CAP) {
            int s = e * CAP + pos;
            g_slot[idx] = s;
            g_slot_token[s] = idx >> 1;
        } else g_slot[idx] = -1;
    }

    int le = tid & 7, chunk = tid >> 3;
    if (tid < 256) {
        float s = 0.f;
        for (int b2 = chunk * 64; b2 < (chunk + 1) * 64; b2++)
            s += g_prob_part[b2 * E_NUM + le];
        ps[chunk][le] = s;
    }
    __syncthreads();
    for (int off = 16; off > 0; off >>= 1) {
        if (tid < 256 && chunk < off) ps[chunk][le] += ps[chunk + off][le];
        __syncthreads();
    }
    if (tid == 0 && out_loss) {
        float tot = 0.f;
#pragma unroll
        for (int ee = 0; ee < E_NUM; ee++) {
            float p = ps[0][ee] / (float)NTOK;
            float f = (float)sc[1023 * E_NUM + ee] / (float)NK;
            tot += p * f;
        }
        *out_loss = (float)E_NUM * tot;
    }
}

// ============================================================
// GEMM tiling: 128x128 block tile, BK=32, 80B-padded smem rows,
// single-barrier depth-3 pipeline over 4 slots.
// ============================================================
#define LDSROW 80
#define CSZ    (128 * LDSROW)   // 10240 B per component tile

// ============================================================
// 4) GEMM1: h = silu(Xg.fc1^T) * (Xg.gating^T), K=1024
//    8 warps, 2x4 of 64x32 dual-acc; all fragments loaded per slab
// ============================================================
__global__ __launch_bounds__(256, 1) void gemm1_mma()
{
    extern __shared__ char smem[];
    int e = blockIdx.z;
    int kept = g_kept[e];
    int m0 = blockIdx.x * 128;
    if (m0 >= kept) return;
    int n0 = blockIdx.y * 128;

    uint32_t sb = smem_u32(smem);
    int tid = threadIdx.x, lane = tid & 31, wid = tid >> 5;
    int wm = wid & 1, wn = wid >> 1;

    const __half* gsrc[6];
    uint32_t sdst[6];
#pragma unroll
    for (int ci = 0; ci < 2; ci++) {
        int c = tid + ci * 256;
        int row = c >> 2, kc = c & 3;
        int tok = g_slot_token[e * CAP + m0 + row] & (NTOK - 1);
        size_t ar = (size_t)tok * IN_D + kc * 8;
        size_t br = ((size_t)e * HD + n0 + row) * IN_D + kc * 8;
        gsrc[ci * 3 + 0] = g_xh + ar;
        gsrc[ci * 3 + 1] = g_w1h + br;
        gsrc[ci * 3 + 2] = g_wgh + br;
        uint32_t sd = sb + row * LDSROW + kc * 16;
#pragma unroll
        for (int comp = 0; comp < 3; comp++) sdst[ci * 3 + comp] = sd + comp * CSZ;
    }

    const int STG = 3 * CSZ;   // 30720 per slot, 4 slots
    auto load_stage = [&](int slab, int st) {
        int ko = slab * 32;
        uint32_t so = st * STG;
#pragma unroll
        for (int i = 0; i < 6; i++) CPA16(sdst[i] + so, gsrc[i] + ko);
        asm volatile("cp.async.commit_group;" ::: "memory");
    };
    load_stage(0, 0);
    load_stage(1, 1);
    load_stage(2, 2);

    uint32_t a_off[4], b_off[2];
#pragma unroll
    for (int mi = 0; mi < 4; mi++)
        a_off[mi] = (wm * 64 + mi * 16 + (lane & 15)) * LDSROW + (lane >> 4) * 16;
#pragma unroll
    for (int ni = 0; ni < 2; ni++)
        b_off[ni] = (wn * 32 + ni * 16 + (lane & 7) + ((lane >> 4) << 3)) * LDSROW
                    + ((lane >> 3) & 1) * 16;

    float acc1[4][4][4], acc2[4][4][4];
#pragma unroll
    for (int mi = 0; mi < 4; mi++)
#pragma unroll
        for (int nj = 0; nj < 4; nj++)
#pragma unroll
            for (int q = 0; q < 4; q++) { acc1[mi][nj][q] = 0.f; acc2[mi][nj][q] = 0.f; }

    for (int s = 0; s < 32; s++) {
        int st = s & 3;
        if (s < 29) asm volatile("cp.async.wait_group 2;" ::: "memory");
        else        asm volatile("cp.async.wait_group 0;" ::: "memory");
        __syncthreads();
        if (s < 29) load_stage(s + 3, (s + 3) & 3);
        uint32_t base = sb + st * STG;

        // load ALL fragments for both k16 steps, then MMA-burst
        uint32_t Ah[2][4][4], B1[2][2][4], B2[2][2][4];
#pragma unroll
        for (int ks = 0; ks < 2; ks++) {
            uint32_t kb = ks * 32;
#pragma unroll
            for (int mi = 0; mi < 4; mi++) LDSM4(Ah[ks][mi], base + a_off[mi] + kb);
#pragma unroll
            for (int ni = 0; ni < 2; ni++) LDSM4(B1[ks][ni], base + CSZ + b_off[ni] + kb);
#pragma unroll
            for (int ni = 0; ni < 2; ni++) LDSM4(B2[ks][ni], base + 2 * CSZ + b_off[ni] + kb);
        }
#pragma unroll
        for (int ks = 0; ks < 2; ks++)
#pragma unroll
            for (int mi = 0; mi < 4; mi++)
#pragma unroll
                for (int ni = 0; ni < 2; ni++)
#pragma unroll
                    for (int hh = 0; hh < 2; hh++) {
                        int nj = ni * 2 + hh;
                        MMA_F16(acc1[mi][nj], Ah[ks][mi], B1[ks][ni] + hh * 2);
                        MMA_F16(acc2[mi][nj], Ah[ks][mi], B2[ks][ni] + hh * 2);
                    }
    }

    // SwiGLU epilogue -> fp16 h
#pragma unroll
    for (int mi = 0; mi < 4; mi++) {
        int rbase = m0 + wm * 64 + mi * 16 + (lane >> 2);
#pragma unroll
        for (int rr = 0; rr < 2; rr++) {
            int r = rbase + rr * 8;
            if (r < kept) {
                size_t ro = (size_t)(e * CAP + r) * HD;
#pragma unroll
                for (int nj = 0; nj < 4; nj++) {
                    int col = n0 + wn * 32 + nj * 8 + (lane & 3) * 2;
                    float v0 = acc1[mi][nj][rr * 2 + 0], v1 = acc1[mi][nj][rr * 2 + 1];
                    float g0 = acc2[mi][nj][rr * 2 + 0], g1 = acc2[mi][nj][rr * 2 + 1];
                    float h0 = v0 / (1.f + __expf(-v0)) * g0;
                    float h1 = v1 / (1.f + __expf(-v1)) * g1;
                    *(__half2*)(g_hh + ro + col) =
                        __halves2half2(__float2half_rn(h0), __float2half_rn(h1));
                }
            }
        }
    }
}

// ============================================================
// 5) GEMM2: out = H . fc2^T, K=2048
//    128 threads, 2x2 warps of 64x64; 2 CTAs/SM
// ============================================================
__global__ __launch_bounds__(128, 2) void gemm2_mma()
{
    extern __shared__ char smem[];
    int e = blockIdx.z;
    int kept = g_kept[e];
    int m0 = blockIdx.x * 128;
    if (m0 >= kept) return;
    int n0 = blockIdx.y * 128;

    uint32_t sb = smem_u32(smem);
    int tid = threadIdx.x, lane = tid & 31, wid = tid >> 5;
    int wm = wid & 1, wn = wid >> 1;   // 2x2 of 64x64

    const __half* gsrc[8];
    uint32_t sdst[8];
#pragma unroll
    for (int ci = 0; ci < 4; ci++) {
        int c = tid + ci * 128;
        int row = c >> 2, kc = c & 3;
        size_t ar = (size_t)(e * CAP + m0 + row) * HD + kc * 8;
        size_t br = ((size_t)e * IN_D + n0 + row) * HD + kc * 8;
        gsrc[ci * 2 + 0] = g_hh + ar;
        gsrc[ci * 2 + 1] = g_w2h + br;
        uint32_t sd = sb + row * LDSROW + kc * 16;
        sdst[ci * 2 + 0] = sd;
        sdst[ci * 2 + 1] = sd + CSZ;
    }

    const int STG = 2 * CSZ;   // 20480 per slot, 4 slots
    auto load_stage = [&](int slab, int st) {
        int ko = slab * 32;
        uint32_t so = st * STG;
#pragma unroll
        for (int i = 0; i < 8; i++) CPA16(sdst[i] + so, gsrc[i] + ko);
        asm volatile("cp.async.commit_group;" ::: "memory");
    };
    load_stage(0, 0);
    load_stage(1, 1);
    load_stage(2, 2);

    uint32_t a_off[4], b_off[4];
#pragma unroll
    for (int mi = 0; mi < 4; mi++)
        a_off[mi] = (wm * 64 + mi * 16 + (lane & 15)) * LDSROW + (lane >> 4) * 16;
#pragma unroll
    for (int ni = 0; ni < 4; ni++)
        b_off[ni] = (wn * 64 + ni * 16 + (lane & 7) + ((lane >> 4) << 3)) * LDSROW
                    + ((lane >> 3) & 1) * 16;

    float acc[4][8][4];
#pragma unroll
    for (int mi = 0; mi < 4; mi++)
#pragma unroll
        for (int nj = 0; nj < 8; nj++)
#pragma unroll
            for (int q = 0; q < 4; q++) acc[mi][nj][q] = 0.f;

    for (int s = 0; s < 64; s++) {
        int st = s & 3;
        if (s < 61) asm volatile("cp.async.wait_group 2;" ::: "memory");
        else        asm volatile("cp.async.wait_group 0;" ::: "memory");
        __syncthreads();
        if (s < 61) load_stage(s + 3, (s + 3) & 3);
        uint32_t base = sb + st * STG;

#pragma unroll
        for (int ks = 0; ks < 2; ks++) {
            uint32_t kb = ks * 32;
            uint32_t Ah[4][4], B[4][4];
#pragma unroll
            for (int mi = 0; mi < 4; mi++) LDSM4(Ah[mi], base + a_off[mi] + kb);
#pragma unroll
            for (int ni = 0; ni < 4; ni++) LDSM4(B[ni], base + CSZ + b_off[ni] + kb);
#pragma unroll
            for (int mi = 0; mi < 4; mi++)
#pragma unroll
                for (int ni = 0; ni < 4; ni++)
#pragma unroll
                    for (int hh = 0; hh < 2; hh++)
                        MMA_F16(acc[mi][ni * 2 + hh], Ah[mi], B[ni] + hh * 2);
        }
    }

#pragma unroll
    for (int mi = 0; mi < 4; mi++) {
        int rbase = m0 + wm * 64 + mi * 16 + (lane >> 2);
#pragma unroll
        for (int rr = 0; rr < 2; rr++) {
            int r = rbase + rr * 8;
            if (r < kept) {
                size_t ro = (size_t)(e * CAP + r) * IN_D;
#pragma unroll
                for (int nj = 0; nj < 8; nj++) {
                    int col = n0 + wn * 64 + nj * 8 + (lane & 3) * 2;
                    *(__half2*)(g_buf_out + ro + col) =
                        __halves2half2(__float2half_rn(acc[mi][nj][rr * 2 + 0]),
                                       __float2half_rn(acc[mi][nj][rr * 2 + 1]));
                }
            }
        }
    }
}

// ============================================================
// 6) combine (fp16 buf)
// ============================================================
__global__ __launch_bounds__(256) void combine_kernel(float* __restrict__ out)
{
    int t = blockIdx.x;
    int s1 = g_slot[2 * t];
    int s2 = g_slot[2 * t + 1];
    float w1 = (s1 >= 0) ? g_w[2 * t] : 0.f;
    float w2 = (s2 >= 0) ? g_w[2 * t + 1] : 0.f;
    const uint2* r1 = (s1 >= 0) ? (const uint2*)(g_buf_out + (size_t)s1 * IN_D) : nullptr;
    const uint2* r2 = (s2 >= 0) ? (const uint2*)(g_buf_out + (size_t)s2 * IN_D) : nullptr;

    int d = threadIdx.x;
    float4 v = make_float4(0, 0, 0, 0);
    if (r1) {
        uint2 a = r1[d];
        float2 p = __half22float2(*reinterpret_cast<__half2*>(&a.x));
        float2 q = __half22float2(*reinterpret_cast<__half2*>(&a.y));
        v.x += w1 * p.x; v.y += w1 * p.y; v.z += w1 * q.x; v.w += w1 * q.y;
    }
    if (r2) {
        uint2 a = r2[d];
        float2 p = __half22float2(*reinterpret_cast<__half2*>(&a.x));
        float2 q = __half22float2(*reinterpret_cast<__half2*>(&a.y));
        v.x += w2 * p.x; v.y += w2 * p.y; v.z += w2 * q.x; v.w += w2 * q.y;
    }
    ((float4*)(out + (size_t)t * IN_D))[d] = v;
}

// ============================================================
extern "C" void kernel_launch(void* const* d_in, const int* in_sizes, int n_in,
                              void* d_out, int out_size)
{
    const float* x      = (const float*)d_in[0];
    const float* gate_w = (const float*)d_in[1];
    const float* fc1_w  = (const float*)d_in[2];
    const float* gating = (const float*)d_in[3];
    const float* fc2_w  = (const float*)d_in[4];
    float* out = (float*)d_out;
    float* loss_ptr = (out_size > NTOK * IN_D) ? out + (size_t)NTOK * IN_D : nullptr;

    const int smem1 = 4 * 3 * CSZ;   // 122880 (1 CTA/SM)
    const int smem2 = 4 * 2 * CSZ;   // 81920  (2 CTAs/SM)
    cudaFuncSetAttribute(gemm1_mma, cudaFuncAttributeMaxDynamicSharedMemorySize, smem1);
    cudaFuncSetAttribute(gemm2_mma, cudaFuncAttributeMaxDynamicSharedMemorySize, smem2);

    const int n8 = NTOK * IN_D / 8;
    prep_kernel<<<ROUTE_BLOCKS + 8192, 256>>>(x, gate_w,
                                              (const float4*)x,
                                              (const float4*)fc1_w,
                                              (const float4*)gating,
                                              (const float4*)fc2_w, n8);

    dispatch_kernel<<<1, 1024>>>(loss_ptr);
    gemm1_mma<<<dim3(CAP / 128, HD / 128, E_NUM), 256, smem1>>>();
    gemm2_mma<<<dim3(CAP / 128, IN_D / 128, E_NUM), 128, smem2>>>();
    combine_kernel<<<NTOK, 256>>>(out);
}

// round 15
// speedup vs baseline: 1.3238x; 1.1559x over previous
#include <cuda_runtime.h>
#include <cuda_bf16.h>
#include <cuda_fp16.h>
#include <cstdint>
#include <math.h>

// ---------------- problem constants ----------------
#define E_NUM      8
#define TOPK       2
#define IN_D       1024
#define HD         2048
#define NTOK       16384
#define NK         32768
#define CAP        5120
#define ROUTE_BLOCKS 2048

// ---------------- device scratch ----------------
__device__ __half g_xh[(size_t)NTOK * IN_D];
__device__ __half g_w1h[(size_t)E_NUM * HD * IN_D];
__device__ __half g_wgh[(size_t)E_NUM * HD * IN_D];
__device__ __half g_w2h[(size_t)E_NUM * IN_D * HD];
__device__ __half g_hh[(size_t)E_NUM * CAP * HD];
__device__ __half g_buf_out[(size_t)E_NUM * CAP * IN_D];
__device__ int   g_exp[NK];
__device__ float g_w[NK];
__device__ int   g_slot[NK];
__device__ int   g_slot_token[E_NUM * CAP];
__device__ int   g_counts[E_NUM];
__device__ int   g_kept[E_NUM];
__device__ float g_prob_part[ROUTE_BLOCKS * E_NUM];

// ---------------- PTX helpers ----------------
__device__ __forceinline__ uint32_t smem_u32(const void* p) {
    uint32_t a;
    asm("{ .reg .u64 t; cvta.to.shared.u64 t, %1; cvt.u32.u64 %0, t; }" : "=r"(a) : "l"(p));
    return a;
}

#define CPA16(dst, src) \
    asm volatile("cp.async.cg.shared.global [%0], [%1], 16;" :: "r"(dst), "l"(src) : "memory")

#define LDSM4(r, addr) \
    asm volatile("ldmatrix.sync.aligned.m8n8.x4.shared.b16 {%0,%1,%2,%3}, [%4];" \
        : "=r"((r)[0]), "=r"((r)[1]), "=r"((r)[2]), "=r"((r)[3]) : "r"(addr))

#define MMA_F16(d, a, bb) \
    asm volatile("mma.sync.aligned.m16n8k16.row.col.f32.f16.f16.f32 " \
        "{%0,%1,%2,%3}, {%4,%5,%6,%7}, {%8,%9}, {%0,%1,%2,%3};" \
        : "+f"((d)[0]), "+f"((d)[1]), "+f"((d)[2]), "+f"((d)[3]) \
        : "r"((a)[0]), "r"((a)[1]), "r"((a)[2]), "r"((a)[3]), \
          "r"((bb)[0]), "r"((bb)[1]))

__device__ __forceinline__ uint32_t pack_h2(float a, float b) {
    __half2 h = __halves2half2(__float2half_rn(a), __float2half_rn(b));
    return *reinterpret_cast<uint32_t*>(&h);
}

// ============================================================
// 0+1) prep: routing (blocks 0..2047) + fp32->fp16 convert
// ============================================================
__global__ __launch_bounds__(256) void prep_kernel(const float* __restrict__ x,
                                                   const float* __restrict__ gate_w,
                                                   const float4* __restrict__ x4,
                                                   const float4* __restrict__ w14,
                                                   const float4* __restrict__ wg4,
                                                   const float4* __restrict__ w24,
                                                   int n8)
{
    __shared__ float sg[E_NUM * IN_D];   // 32KB (route only)
    __shared__ float pp[8][E_NUM];

    if (blockIdx.x < ROUTE_BLOCKS) {
        for (int i = threadIdx.x; i < E_NUM * IN_D; i += blockDim.x) sg[i] = gate_w[i];
        __syncthreads();

        int w = threadIdx.x >> 5, lane = threadIdx.x & 31;
        int t = blockIdx.x * 8 + w;
        const float* xr = x + (size_t)t * IN_D;
        float acc[E_NUM];
#pragma unroll
        for (int e = 0; e < E_NUM; e++) acc[e] = 0.f;
        for (int j = 0; j < IN_D / 32; j++) {
            float xv = xr[lane + j * 32];
#pragma unroll
            for (int e = 0; e < E_NUM; e++) acc[e] += xv * sg[e * IN_D + lane + j * 32];
        }
#pragma unroll
        for (int off = 16; off > 0; off >>= 1)
#pragma unroll
            for (int e = 0; e < E_NUM; e++) acc[e] += __shfl_down_sync(0xffffffffu, acc[e], off);

        if (lane == 0) {
            float m = acc[0];
#pragma unroll
            for (int e = 1; e < E_NUM; e++) m = fmaxf(m, acc[e]);
            float p[E_NUM], s = 0.f;
#pragma unroll
            for (int e = 0; e < E_NUM; e++) { p[e] = expf(acc[e] - m); s += p[e]; }
            float inv = 1.f / s;
#pragma unroll
            for (int e = 0; e < E_NUM; e++) p[e] *= inv;
            int e1 = 0;
#pragma unroll
            for (int e = 1; e < E_NUM; e++) if (p[e] > p[e1]) e1 = e;
            int e2 = (e1 == 0) ? 1 : 0;
#pragma unroll
            for (int e = 0; e < E_NUM; e++) if (e != e1 && p[e] > p[e2]) e2 = e;
            float denom = p[e1] + p[e2] + 1e-9f;
            g_exp[2 * t] = e1; g_exp[2 * t + 1] = e2;
            g_w[2 * t] = p[e1] / denom; g_w[2 * t + 1] = p[e2] / denom;
#pragma unroll
            for (int e = 0; e < E_NUM; e++) pp[w][e] = p[e];
        }
        __syncthreads();
        if (threadIdx.x < E_NUM) {
            float s = 0.f;
            for (int ww = 0; ww < 8; ww++) s += pp[ww][threadIdx.x];
            g_prob_part[blockIdx.x * E_NUM + threadIdx.x] = s;
        }
        return;
    }

    int rb  = blockIdx.x - ROUTE_BLOCKS;
    int seg = rb >> 11;
    int b   = rb & 2047;
    const float4* in;
    __half* dst;
    switch (seg) {
        case 0: in = x4;  dst = g_xh;  break;
        case 1: in = w14; dst = g_w1h; break;
        case 2: in = wg4; dst = g_wgh; break;
        default: in = w24; dst = g_w2h; break;
    }
    uint4* d8 = (uint4*)dst;
    for (int i = b * blockDim.x + threadIdx.x; i < n8; i += 2048 * blockDim.x) {
        float4 a = in[2 * i], c = in[2 * i + 1];
        uint4 o;
        o.x = pack_h2(a.x, a.y);
        o.y = pack_h2(a.z, a.w);
        o.z = pack_h2(c.x, c.y);
        o.w = pack_h2(c.z, c.w);
        d8[i] = o;
    }
}

// ============================================================
// 2) dispatch + loss (fused tail)
// ============================================================
__global__ __launch_bounds__(1024) void dispatch_kernel(float* out_loss)
{
    __shared__ int sc[1024 * E_NUM];
    __shared__ float ps[32][E_NUM];
    int tid = threadIdx.x, base = tid * 32;
    int h[E_NUM];
#pragma unroll
    for (int e = 0; e < E_NUM; e++) h[e] = 0;
    for (int i = 0; i < 32; i++) h[g_exp[base + i]]++;
#pragma unroll
    for (int e = 0; e < E_NUM; e++) sc[tid * E_NUM + e] = h[e];
    __syncthreads();
    for (int off = 1; off < 1024; off <<= 1) {
        int v[E_NUM];
        if (tid >= off)
#pragma unroll
            for (int e = 0; e < E_NUM; e++) v[e] = sc[(tid - off) * E_NUM + e];
        __syncthreads();
        if (tid >= off)
#pragma unroll
            for (int e = 0; e < E_NUM; e++) sc[tid * E_NUM + e] += v[e];
        __syncthreads();
    }
    int basec[E_NUM];
#pragma unroll
    for (int e = 0; e < E_NUM; e++) basec[e] = sc[tid * E_NUM + e] - h[e];
    if (tid == 1023)
#pragma unroll
        for (int e = 0; e < E_NUM; e++) {
            int c = sc[tid * E_NUM + e];
            g_counts[e] = c;
            g_kept[e] = (c < CAP) ? c : CAP;
        }
    for (int i = 0; i < 32; i++) {
        int idx = base + i;
        int e = g_exp[idx];
        int pos = basec[e]++;
        if (pos < CAP) {
            int s = e * CAP + pos;
            g_slot[idx] = s;
            g_slot_token[s] = idx >> 1;
        } else g_slot[idx] = -1;
    }

    int le = tid & 7, chunk = tid >> 3;
    if (tid < 256) {
        float s = 0.f;
        for (int b2 = chunk * 64; b2 < (chunk + 1) * 64; b2++)
            s += g_prob_part[b2 * E_NUM + le];
        ps[chunk][le] = s;
    }
    __syncthreads();
    for (int off = 16; off > 0; off >>= 1) {
        if (tid < 256 && chunk < off) ps[chunk][le] += ps[chunk + off][le];
        __syncthreads();
    }
    if (tid == 0 && out_loss) {
        float tot = 0.f;
#pragma unroll
        for (int ee = 0; ee < E_NUM; ee++) {
            float p = ps[0][ee] / (float)NTOK;
            float f = (float)sc[1023 * E_NUM + ee] / (float)NK;
            tot += p * f;
        }
        *out_loss = (float)E_NUM * tot;
    }
}

// ============================================================
// GEMM tiling: 80B-padded smem rows, single-barrier depth-3
// pipeline over 4 slots, fragment-burst then MMA-burst.
// ============================================================
#define LDSROW 80
#define CSZ    (128 * LDSROW)   // 10240 B per 128-row component
#define HCSZ   (64 * LDSROW)    // 5120 B per 64-row component

// ============================================================
// 4) GEMM1: h = silu(Xg.fc1^T) * (Xg.gating^T), K=1024
//    block 128x64 dual-B; 128 threads (2x2 warps of 64x32-dual);
//    2 CTAs/SM. Slot: A(128)=10240, B1(64)=5120, B2(64)=5120
// ============================================================
__global__ __launch_bounds__(128, 2) void gemm1_mma()
{
    extern __shared__ char smem[];
    int e = blockIdx.z;
    int kept = g_kept[e];
    int m0 = blockIdx.x * 128;
    if (m0 >= kept) return;
    int n0 = blockIdx.y * 64;

    uint32_t sb = smem_u32(smem);
    int tid = threadIdx.x, lane = tid & 31, wid = tid >> 5;
    int wm = wid & 1, wn = wid >> 1;   // 2x2 warps: 64 m x 32 n (dual)

    // loaders: A rows 128 x 4 chunks = 512 (4/thread); B1,B2 rows 64 x 4 = 256 each (2/thread)
    const __half* gsrcA[4];
    uint32_t sdstA[4];
#pragma unroll
    for (int ci = 0; ci < 4; ci++) {
        int c = tid + ci * 128;
        int row = c >> 2, kc = c & 3;
        int tok = g_slot_token[e * CAP + m0 + row] & (NTOK - 1);
        gsrcA[ci] = g_xh + (size_t)tok * IN_D + kc * 8;
        sdstA[ci] = sb + row * LDSROW + kc * 16;
    }
    const __half* gsrcB[4];
    uint32_t sdstB[4];
#pragma unroll
    for (int ci = 0; ci < 2; ci++) {
        int c = tid + ci * 128;
        int row = c >> 2, kc = c & 3;
        size_t br = ((size_t)e * HD + n0 + row) * IN_D + kc * 8;
        gsrcB[ci * 2 + 0] = g_w1h + br;
        gsrcB[ci * 2 + 1] = g_wgh + br;
        uint32_t sd = sb + CSZ + row * LDSROW + kc * 16;
        sdstB[ci * 2 + 0] = sd;
        sdstB[ci * 2 + 1] = sd + HCSZ;
    }

    const int STG = CSZ + 2 * HCSZ;   // 20480 per slot, 4 slots = 81920
    auto load_stage = [&](int slab, int st) {
        int ko = slab * 32;
        uint32_t so = st * STG;
#pragma unroll
        for (int i = 0; i < 4; i++) CPA16(sdstA[i] + so, gsrcA[i] + ko);
#pragma unroll
        for (int i = 0; i < 4; i++) CPA16(sdstB[i] + so, gsrcB[i] + ko);
        asm volatile("cp.async.commit_group;" ::: "memory");
    };
    load_stage(0, 0);
    load_stage(1, 1);
    load_stage(2, 2);

    uint32_t a_off[4], b_off[2];
#pragma unroll
    for (int mi = 0; mi < 4; mi++)
        a_off[mi] = (wm * 64 + mi * 16 + (lane & 15)) * LDSROW + (lane >> 4) * 16;
#pragma unroll
    for (int ni = 0; ni < 2; ni++)
        b_off[ni] = (wn * 32 + ni * 16 + (lane & 7) + ((lane >> 4) << 3)) * LDSROW
                    + ((lane >> 3) & 1) * 16;

    float acc1[4][4][4], acc2[4][4][4];
#pragma unroll
    for (int mi = 0; mi < 4; mi++)
#pragma unroll
        for (int nj = 0; nj < 4; nj++)
#pragma unroll
            for (int q = 0; q < 4; q++) { acc1[mi][nj][q] = 0.f; acc2[mi][nj][q] = 0.f; }

    for (int s = 0; s < 32; s++) {
        int st = s & 3;
        if (s < 29) asm volatile("cp.async.wait_group 2;" ::: "memory");
        else        asm volatile("cp.async.wait_group 0;" ::: "memory");
        __syncthreads();
        if (s < 29) load_stage(s + 3, (s + 3) & 3);
        uint32_t base = sb + st * STG;

        uint32_t Ah[2][4][4], B1[2][2][4], B2[2][2][4];
#pragma unroll
        for (int ks = 0; ks < 2; ks++) {
            uint32_t kb = ks * 32;
#pragma unroll
            for (int mi = 0; mi < 4; mi++) LDSM4(Ah[ks][mi], base + a_off[mi] + kb);
#pragma unroll
            for (int ni = 0; ni < 2; ni++) LDSM4(B1[ks][ni], base + CSZ + b_off[ni] + kb);
#pragma unroll
            for (int ni = 0; ni < 2; ni++) LDSM4(B2[ks][ni], base + CSZ + HCSZ + b_off[ni] + kb);
        }
#pragma unroll
        for (int ks = 0; ks < 2; ks++)
#pragma unroll
            for (int mi = 0; mi < 4; mi++)
#pragma unroll
                for (int ni = 0; ni < 2; ni++)
#pragma unroll
                    for (int hh = 0; hh < 2; hh++) {
                        int nj = ni * 2 + hh;
                        MMA_F16(acc1[mi][nj], Ah[ks][mi], B1[ks][ni] + hh * 2);
                        MMA_F16(acc2[mi][nj], Ah[ks][mi], B2[ks][ni] + hh * 2);
                    }
    }

    // SwiGLU epilogue -> fp16 h
#pragma unroll
    for (int mi = 0; mi < 4; mi++) {
        int rbase = m0 + wm * 64 + mi * 16 + (lane >> 2);
#pragma unroll
        for (int rr = 0; rr < 2; rr++) {
            int r = rbase + rr * 8;
            if (r < kept) {
                size_t ro = (size_t)(e * CAP + r) * HD;
#pragma unroll
                for (int nj = 0; nj < 4; nj++) {
                    int col = n0 + wn * 32 + nj * 8 + (lane & 3) * 2;
                    float v0 = acc1[mi][nj][rr * 2 + 0], v1 = acc1[mi][nj][rr * 2 + 1];
                    float g0 = acc2[mi][nj][rr * 2 + 0], g1 = acc2[mi][nj][rr * 2 + 1];
                    float h0 = v0 / (1.f + __expf(-v0)) * g0;
                    float h1 = v1 / (1.f + __expf(-v1)) * g1;
                    *(__half2*)(g_hh + ro + col) =
                        __halves2half2(__float2half_rn(h0), __float2half_rn(h1));
                }
            }
        }
    }
}

// ============================================================
// 5) GEMM2: out = H . fc2^T, K=2048
//    128 threads, 2x2 warps of 64x64; 2 CTAs/SM
// ============================================================
__global__ __launch_bounds__(128, 2) void gemm2_mma()
{
    extern __shared__ char smem[];
    int e = blockIdx.z;
    int kept = g_kept[e];
    int m0 = blockIdx.x * 128;
    if (m0 >= kept) return;
    int n0 = blockIdx.y * 128;

    uint32_t sb = smem_u32(smem);
    int tid = threadIdx.x, lane = tid & 31, wid = tid >> 5;
    int wm = wid & 1, wn = wid >> 1;   // 2x2 of 64x64

    const __half* gsrc[8];
    uint32_t sdst[8];
#pragma unroll
    for (int ci = 0; ci < 4; ci++) {
        int c = tid + ci * 128;
        int row = c >> 2, kc = c & 3;
        size_t ar = (size_t)(e * CAP + m0 + row) * HD + kc * 8;
        size_t br = ((size_t)e * IN_D + n0 + row) * HD + kc * 8;
        gsrc[ci * 2 + 0] = g_hh + ar;
        gsrc[ci * 2 + 1] = g_w2h + br;
        uint32_t sd = sb + row * LDSROW + kc * 16;
        sdst[ci * 2 + 0] = sd;
        sdst[ci * 2 + 1] = sd + CSZ;
    }

    const int STG = 2 * CSZ;   // 20480 per slot, 4 slots
    auto load_stage = [&](int slab, int st) {
        int ko = slab * 32;
        uint32_t so = st * STG;
#pragma unroll
        for (int i = 0; i < 8; i++) CPA16(sdst[i] + so, gsrc[i] + ko);
        asm volatile("cp.async.commit_group;" ::: "memory");
    };
    load_stage(0, 0);
    load_stage(1, 1);
    load_stage(2, 2);

    uint32_t a_off[4], b_off[4];
#pragma unroll
    for (int mi = 0; mi < 4; mi++)
        a_off[mi] = (wm * 64 + mi * 16 + (lane & 15)) * LDSROW + (lane >> 4) * 16;
#pragma unroll
    for (int ni = 0; ni < 4; ni++)
        b_off[ni] = (wn * 64 + ni * 16 + (lane & 7) + ((lane >> 4) << 3)) * LDSROW
                    + ((lane >> 3) & 1) * 16;

    float acc[4][8][4];
#pragma unroll
    for (int mi = 0; mi < 4; mi++)
#pragma unroll
        for (int nj = 0; nj < 8; nj++)
#pragma unroll
            for (int q = 0; q < 4; q++) acc[mi][nj][q] = 0.f;

    for (int s = 0; s < 64; s++) {
        int st = s & 3;
        if (s < 61) asm volatile("cp.async.wait_group 2;" ::: "memory");
        else        asm volatile("cp.async.wait_group 0;" ::: "memory");
        __syncthreads();
        if (s < 61) load_stage(s + 3, (s + 3) & 3);
        uint32_t base = sb + st * STG;

#pragma unroll
        for (int ks = 0; ks < 2; ks++) {
            uint32_t kb = ks * 32;
            uint32_t Ah[4][4], B[4][4];
#pragma unroll
            for (int mi = 0; mi < 4; mi++) LDSM4(Ah[mi], base + a_off[mi] + kb);
#pragma unroll
            for (int ni = 0; ni < 4; ni++) LDSM4(B[ni], base + CSZ + b_off[ni] + kb);
#pragma unroll
            for (int mi = 0; mi < 4; mi++)
#pragma unroll
                for (int ni = 0; ni < 4; ni++)
#pragma unroll
                    for (int hh = 0; hh < 2; hh++)
                        MMA_F16(acc[mi][ni * 2 + hh], Ah[mi], B[ni] + hh * 2);
        }
    }

#pragma unroll
    for (int mi = 0; mi < 4; mi++) {
        int rbase = m0 + wm * 64 + mi * 16 + (lane >> 2);
#pragma unroll
        for (int rr = 0; rr < 2; rr++) {
            int r = rbase + rr * 8;
            if (r < kept) {
                size_t ro = (size_t)(e * CAP + r) * IN_D;
#pragma unroll
                for (int nj = 0; nj < 8; nj++) {
                    int col = n0 + wn * 64 + nj * 8 + (lane & 3) * 2;
                    *(__half2*)(g_buf_out + ro + col) =
                        __halves2half2(__float2half_rn(acc[mi][nj][rr * 2 + 0]),
                                       __float2half_rn(acc[mi][nj][rr * 2 + 1]));
                }
            }
        }
    }
}

// ============================================================
// 6) combine (fp16 buf)
// ============================================================
__global__ __launch_bounds__(256) void combine_kernel(float* __restrict__ out)
{
    int t = blockIdx.x;
    int s1 = g_slot[2 * t];
    int s2 = g_slot[2 * t + 1];
    float w1 = (s1 >= 0) ? g_w[2 * t] : 0.f;
    float w2 = (s2 >= 0) ? g_w[2 * t + 1] : 0.f;
    const uint2* r1 = (s1 >= 0) ? (const uint2*)(g_buf_out + (size_t)s1 * IN_D) : nullptr;
    const uint2* r2 = (s2 >= 0) ? (const uint2*)(g_buf_out + (size_t)s2 * IN_D) : nullptr;

    int d = threadIdx.x;
    float4 v = make_float4(0, 0, 0, 0);
    if (r1) {
        uint2 a = r1[d];
        float2 p = __half22float2(*reinterpret_cast<__half2*>(&a.x));
        float2 q = __half22float2(*reinterpret_cast<__half2*>(&a.y));
        v.x += w1 * p.x; v.y += w1 * p.y; v.z += w1 * q.x; v.w += w1 * q.y;
    }
    if (r2) {
        uint2 a = r2[d];
        float2 p = __half22float2(*reinterpret_cast<__half2*>(&a.x));
        float2 q = __half22float2(*reinterpret_cast<__half2*>(&a.y));
        v.x += w2 * p.x; v.y += w2 * p.y; v.z += w2 * q.x; v.w += w2 * q.y;
    }
    ((float4*)(out + (size_t)t * IN_D))[d] = v;
}

// ============================================================
extern "C" void kernel_launch(void* const* d_in, const int* in_sizes, int n_in,
                              void* d_out, int out_size)
{
    const float* x      = (const float*)d_in[0];
    const float* gate_w = (const float*)d_in[1];
    const float* fc1_w  = (const float*)d_in[2];
    const float* gating = (const float*)d_in[3];
    const float* fc2_w  = (const float*)d_in[4];
    float* out = (float*)d_out;
    float* loss_ptr = (out_size > NTOK * IN_D) ? out + (size_t)NTOK * IN_D : nullptr;

    const int smem1 = 4 * (CSZ + 2 * HCSZ);   // 81920 (2 CTAs/SM)
    const int smem2 = 4 * 2 * CSZ;            // 81920 (2 CTAs/SM)
    cudaFuncSetAttribute(gemm1_mma, cudaFuncAttributeMaxDynamicSharedMemorySize, smem1);
    cudaFuncSetAttribute(gemm2_mma, cudaFuncAttributeMaxDynamicSharedMemorySize, smem2);

    const int n8 = NTOK * IN_D / 8;
    prep_kernel<<<ROUTE_BLOCKS + 8192, 256>>>(x, gate_w,
                                              (const float4*)x,
                                              (const float4*)fc1_w,
                                              (const float4*)gating,
                                              (const float4*)fc2_w, n8);

    dispatch_kernel<<<1, 1024>>>(loss_ptr);
    gemm1_mma<<<dim3(CAP / 128, HD / 64, E_NUM), 128, smem1>>>();
    gemm2_mma<<<dim3(CAP / 128, IN_D / 128, E_NUM), 128, smem2>>>();
    combine_kernel<<<NTOK, 256>>>(out);
}